// round 5
// baseline (speedup 1.0000x reference)
#include <cuda_runtime.h>
#include <cstdint>

// Problem dims
#define B_  4096
#define D_  4624
#define L_  68
#define E_  1024

// GEMM tiling (mma.sync tf32 path — tcgen05 is unavailable: harness compiles
// through compute_103 (non-'a') PTX, which rejects tcgen05/cta_group features)
#define BM 128
#define BN 128
#define BK 32
#define KPAD 36            // smem row stride in u32 -> conflict-free frag loads
#define STAGE_U32 (128 * KPAD)   // 4608 u32 = 18432 B per operand stage
#define THREADS 256

// ---- static scratch (no cudaMalloc allowed) ----
__device__ float g_h  [(size_t)B_ * 2 * E_];   // relu(x@fc11^T)|relu(x@fc12^T), tf32-rounded
__device__ float g_h51[(size_t)B_ * L_];       // decoder branch-0 output
__device__ float g_x32[(size_t)B_ * D_];       // x, tf32-rounded
__device__ float g_w6 [(size_t)D_ * D_];       // fc6_w, tf32-rounded
__device__ float g_w1 [(size_t)2 * E_ * D_];   // fc11_w|fc12_w concat, tf32-rounded
__device__ float g_w2 [(size_t)2 * L_ * E_];   // fc21_w|fc22_w concat, tf32-rounded
__device__ float g_b1 [2 * E_];                // fc11_b|fc12_b concat

// ============================ helpers ============================
__device__ __forceinline__ uint32_t f2tf32(float x) {
    uint32_t r;
    asm("cvt.rna.tf32.f32 %0, %1;" : "=r"(r) : "f"(x));
    return r;
}

__device__ __forceinline__ void mma_tf32(float* c, uint32_t a0, uint32_t a1,
                                         uint32_t a2, uint32_t a3,
                                         uint32_t b0, uint32_t b1) {
    asm volatile(
        "mma.sync.aligned.m16n8k8.row.col.f32.tf32.tf32.f32 "
        "{%0,%1,%2,%3}, {%4,%5,%6,%7}, {%8,%9}, {%0,%1,%2,%3};\n"
        : "+f"(c[0]), "+f"(c[1]), "+f"(c[2]), "+f"(c[3])
        : "r"(a0), "r"(a1), "r"(a2), "r"(a3), "r"(b0), "r"(b1));
}

__device__ __forceinline__ void cp_async16(void* sptr, const void* gptr, int src_size) {
    uint32_t s = (uint32_t)__cvta_generic_to_shared(sptr);
    asm volatile("cp.async.cg.shared.global [%0], [%1], 16, %2;\n"
                 :: "r"(s), "l"(gptr), "r"(src_size));
}
__device__ __forceinline__ void cp_commit() { asm volatile("cp.async.commit_group;\n"); }
template <int N>
__device__ __forceinline__ void cp_wait() { asm volatile("cp.async.wait_group %0;\n" :: "n"(N)); }

// ============================ pre-pass ============================
__global__ void round_tf32_v4(const float4* __restrict__ in, float4* __restrict__ out, int n4) {
    int i = blockIdx.x * blockDim.x + threadIdx.x;
    int stride = gridDim.x * blockDim.x;
    for (; i < n4; i += stride) {
        float4 v = in[i];
        v.x = __uint_as_float(f2tf32(v.x));
        v.y = __uint_as_float(f2tf32(v.y));
        v.z = __uint_as_float(f2tf32(v.z));
        v.w = __uint_as_float(f2tf32(v.w));
        out[i] = v;
    }
}

// ============================ main GEMMs (3-stage cp.async) ============================
// MODE 0: C = round_tf32(relu(A @ W^T + bias))   (encoder fc11|fc12 concat)
// MODE 2: C = sigmoid(outer(h51) @ W^T + bias)   (recon; A synthesized IN REGISTERS)
template <int MODE>
__global__ void __launch_bounds__(THREADS, 2)
gemm_ms(const float* __restrict__ A, int lda,
        const float* __restrict__ W, const float* __restrict__ bias,
        const float* __restrict__ h51,
        float* __restrict__ C, int ldc, int N, int K, int Nw)
{
    extern __shared__ unsigned char smem_raw[];
    uint32_t* sm = reinterpret_cast<uint32_t*>(smem_raw);

    // MODE 0 layout: As = sm[0 .. 3*STAGE), Bs = sm[3*STAGE .. 6*STAGE)
    // MODE 2 layout: h51s = sm[0 .. 128*68), Bs = sm + 128*68
    uint32_t* As   = sm;
    uint32_t* Bs   = (MODE == 0) ? (sm + 3 * STAGE_U32) : (sm + 128 * L_);
    float*    h51s = reinterpret_cast<float*>(sm);

    const int tid  = threadIdx.x;
    const int lane = tid & 31;
    const int warp = tid >> 5;
    const int wm   = warp & 3;          // 4 warps along M
    const int wn   = warp >> 2;         // 2 warps along N
    const int grp  = lane >> 2;
    const int kq   = lane & 3;
    const int m0   = blockIdx.y * BM;
    const int n0   = blockIdx.x * BN;
    const int kt   = (K + BK - 1) / BK;

    if (MODE == 2) {
        for (int idx = tid; idx < BM * L_; idx += THREADS)
            h51s[idx] = h51[(size_t)m0 * L_ + idx];
        __syncthreads();
    }

    auto prefetch = [&](int t) {
        const int s  = t % 3;
        const int k0 = t * BK;
        if (MODE == 0) {
            uint32_t* Ab = As + s * STAGE_U32;
#pragma unroll
            for (int i = 0; i < 4; i++) {
                int q = tid + i * 256;
                int r = q >> 3, cb = q & 7;
                int k = k0 + cb * 4;
                cp_async16(Ab + r * KPAD + cb * 4,
                           A + (size_t)(m0 + r) * lda + k, (k < K) ? 16 : 0);
            }
        }
        uint32_t* Bb = Bs + s * STAGE_U32;
#pragma unroll
        for (int i = 0; i < 4; i++) {
            int q = tid + i * 256;
            int r = q >> 3, cb = q & 7;
            int k = k0 + cb * 4;
            int row = n0 + r;
            const float* src = W + (size_t)(row < Nw ? row : 0) * K + k;
            cp_async16(Bb + r * KPAD + cb * 4, src, (row < Nw && k < K) ? 16 : 0);
        }
        cp_commit();
    };

    float acc[2][8][4] = {};
    const int aBase = wm * 32 + grp;
    const int bBase = wn * 64 + grp;

    auto compute = [&](int buf, int k0) {
        const uint32_t* Bb = Bs + buf * STAGE_U32;

        // MODE 2: per-iter h51 "i-column" cache (i takes <=2 values over a k32 window)
        int   i0 = 0, kb = 0;
        float h_i[4][2];
        if (MODE == 2) {
            i0 = k0 / L_;
            kb = (i0 + 1) * L_;
#pragma unroll
            for (int ri = 0; ri < 4; ri++) {
                int r = wm * 32 + grp + 8 * ri;   // rows: base,+8,+16,+24
                h_i[ri][0] = h51s[r * L_ + i0];
                h_i[ri][1] = (kb < K) ? h51s[r * L_ + i0 + 1] : 0.f;
            }
        }
        const uint32_t* Ab = As + buf * STAGE_U32;

#pragma unroll
        for (int kk = 0; kk < 4; kk++) {
            int k = kk * 8 + kq;
            uint32_t a[2][4];
            if (MODE == 2) {
                // synthesize A fragments in registers: A[m][c] = h[m][c/68]*h[m][c%68]
                int c0 = k0 + k, c1 = c0 + 4;
                int s0 = (c0 >= kb) ? 1 : 0;
                int s1 = (c1 >= kb) ? 1 : 0;
                int j0 = c0 - (s0 ? kb : i0 * L_);
                int j1 = c1 - (s1 ? kb : i0 * L_);
                bool v0 = c0 < K, v1 = c1 < K;
#pragma unroll
                for (int mt = 0; mt < 2; mt++) {
#pragma unroll
                    for (int half = 0; half < 2; half++) {
                        int ri = 2 * mt + half;
                        int r  = wm * 32 + grp + 8 * ri;
                        float p0 = v0 ? h_i[ri][s0] * h51s[r * L_ + j0] : 0.f;
                        float p1 = v1 ? h_i[ri][s1] * h51s[r * L_ + j1] : 0.f;
                        a[mt][half]     = f2tf32(p0);
                        a[mt][half + 2] = f2tf32(p1);
                    }
                }
            } else {
#pragma unroll
                for (int mt = 0; mt < 2; mt++) {
                    int r = aBase + mt * 16;
                    a[mt][0] = Ab[r * KPAD + k];
                    a[mt][1] = Ab[(r + 8) * KPAD + k];
                    a[mt][2] = Ab[r * KPAD + k + 4];
                    a[mt][3] = Ab[(r + 8) * KPAD + k + 4];
                }
            }
#pragma unroll
            for (int nt = 0; nt < 8; nt++) {
                int c = bBase + nt * 8;
                uint32_t b0 = Bb[c * KPAD + k];
                uint32_t b1 = Bb[c * KPAD + k + 4];
#pragma unroll
                for (int mt = 0; mt < 2; mt++)
                    mma_tf32(acc[mt][nt], a[mt][0], a[mt][1], a[mt][2], a[mt][3], b0, b1);
            }
        }
    };

    // 3-stage pipeline, one __syncthreads per iteration
    prefetch(0);
    prefetch(1);
    for (int t = 0; t < kt; t++) {
        if (t < kt - 1) cp_wait<1>(); else cp_wait<0>();
        __syncthreads();
        if (t + 2 < kt) prefetch(t + 2);
        compute(t % 3, t * BK);
    }

    // Epilogue: bias + activation + guarded store
#pragma unroll
    for (int mt = 0; mt < 2; mt++) {
        int row = m0 + wm * 32 + mt * 16 + grp;
#pragma unroll
        for (int nt = 0; nt < 8; nt++) {
            int ncl = wn * 64 + nt * 8 + kq * 2;
#pragma unroll
            for (int e = 0; e < 4; e++) {
                int r   = row + ((e >= 2) ? 8 : 0);
                int col = n0 + ncl + (e & 1);
                if (col < N) {
                    float v = acc[mt][nt][e] + bias[col];
                    if (MODE == 0) {
                        v = v > 0.f ? v : 0.f;
                        v = __uint_as_float(f2tf32(v));   // pre-round for next GEMM
                    } else {
                        v = 1.0f / (1.0f + __expf(-v));
                    }
                    C[(size_t)r * ldc + col] = v;
                }
            }
        }
    }
}

// ============================ head GEMM (mu / logvar) ============================
// C = A @ W^T + b, batched over blockIdx.z; A,W pre-rounded tf32
__global__ void __launch_bounds__(THREADS, 2)
gemm_head(const float* __restrict__ Abase, const float* __restrict__ Wbase,
          const float* __restrict__ bias0, const float* __restrict__ bias1,
          float* __restrict__ Cbase, int batchStrideC)
{
    extern __shared__ unsigned char smem_raw[];
    uint32_t* As = reinterpret_cast<uint32_t*>(smem_raw);
    uint32_t* Bs = As + 2 * BM * KPAD;

    const int tid = threadIdx.x;
    const int m0  = blockIdx.y * BM;
    const int N = L_, K = E_;

    const int z = blockIdx.z;
    const float* A    = Abase + (size_t)z * E_;     // column offset into g_h
    const float* W    = Wbase + (size_t)z * L_ * E_;
    const float* bias = z ? bias1 : bias0;
    float* C          = Cbase + (size_t)z * batchStrideC;

    const int lrow = tid >> 3;
    const int lcol = (tid & 7) * 4;

    auto prefetch = [&](int t) {
        const int buf = t & 1;
        const int k0  = t * BK;
        uint32_t* Ab = As + buf * BM * KPAD;
        uint32_t* Bb = Bs + buf * BN * KPAD;
#pragma unroll
        for (int i = 0; i < 4; i++) {
            const int r = lrow + 32 * i;
            cp_async16(Ab + r * KPAD + lcol, A + (size_t)(m0 + r) * (2 * E_) + k0 + lcol, 16);
            int rr = r < N ? r : 0;
            cp_async16(Bb + r * KPAD + lcol, W + (size_t)rr * K + k0 + lcol,
                       (r < N) ? 16 : 0);
        }
        cp_commit();
    };

    float acc[2][8][4] = {};
    const int lane = tid & 31;
    const int warp = tid >> 5;
    const int wm = warp & 3;
    const int wn = warp >> 2;
    const int aBase = wm * 32 + (lane >> 2);
    const int bBase = wn * 64 + (lane >> 2);
    const int kq = lane & 3;

    auto compute = [&](int buf) {
        const uint32_t* Ab = As + buf * BM * KPAD;
        const uint32_t* Bb = Bs + buf * BN * KPAD;
#pragma unroll
        for (int kk = 0; kk < 4; kk++) {
            int k = kk * 8 + kq;
            uint32_t a[2][4];
#pragma unroll
            for (int mt = 0; mt < 2; mt++) {
                int r = aBase + mt * 16;
                a[mt][0] = Ab[r * KPAD + k];
                a[mt][1] = Ab[(r + 8) * KPAD + k];
                a[mt][2] = Ab[r * KPAD + k + 4];
                a[mt][3] = Ab[(r + 8) * KPAD + k + 4];
            }
#pragma unroll
            for (int nt = 0; nt < 8; nt++) {
                int c = bBase + nt * 8;
                uint32_t b0 = Bb[c * KPAD + k];
                uint32_t b1 = Bb[c * KPAD + k + 4];
#pragma unroll
                for (int mt = 0; mt < 2; mt++)
                    mma_tf32(acc[mt][nt], a[mt][0], a[mt][1], a[mt][2], a[mt][3], b0, b1);
            }
        }
    };

    const int kt = K / BK;
    prefetch(0);
    for (int t = 0; t < kt; t++) {
        if (t + 1 < kt) { prefetch(t + 1); cp_wait<1>(); }
        else            { cp_wait<0>(); }
        __syncthreads();
        compute(t & 1);
        __syncthreads();
    }

#pragma unroll
    for (int mt = 0; mt < 2; mt++) {
        int row = m0 + wm * 32 + mt * 16 + (lane >> 2);
#pragma unroll
        for (int nt = 0; nt < 8; nt++) {
            int ncl = wn * 64 + nt * 8 + kq * 2;
#pragma unroll
            for (int e = 0; e < 4; e++) {
                int r   = row + ((e >= 2) ? 8 : 0);
                int col = ncl + (e & 1);
                if (col < N)
                    C[(size_t)r * N + col] = acc[mt][nt][e] + bias[col];
            }
        }
    }
}

// ============================ mid kernel ============================
// z = mu + eps*exp(0.5*logvar); y = mu@fcy^T+b; decoder branch 0 only (others dead)
__global__ void __launch_bounds__(256, 1)
mid_kernel(const float* __restrict__ mu, const float* __restrict__ logvar,
           const float* __restrict__ eps,
           const float* __restrict__ W3, const float* __restrict__ b3,
           const float* __restrict__ W4, const float* __restrict__ b4,
           const float* __restrict__ W5, const float* __restrict__ b5,
           const float* __restrict__ fcy_w, const float* __restrict__ fcy_b,
           float* __restrict__ h51, float* __restrict__ y)
{
    extern __shared__ unsigned char smem_raw[];
    float* s   = reinterpret_cast<float*>(smem_raw);
    float* sW3 = s;
    float* sW4 = sW3 + L_ * 69;
    float* sW5 = sW4 + L_ * 69;
    float* sb3 = sW5 + L_ * 69;
    float* sb4 = sb3 + L_;
    float* sb5 = sb4 + L_;
    float* zs  = sb5 + L_;
    float* h3s = zs + 8 * L_;
    float* h4s = h3s + 8 * L_;

    const int tid = threadIdx.x;
    for (int idx = tid; idx < L_ * L_; idx += 256) {
        int o = idx / L_, d = idx - o * L_;
        sW3[o * 69 + d] = W3[idx];
        sW4[o * 69 + d] = W4[idx];
        sW5[o * 69 + d] = W5[idx];
    }
    for (int idx = tid; idx < L_; idx += 256) {
        sb3[idx] = b3[idx]; sb4[idx] = b4[idx]; sb5[idx] = b5[idx];
    }
    __syncthreads();

    const int lane = tid & 31, w = tid >> 5;
    const int row = blockIdx.x * 8 + w;
    const float* murow  = mu + (size_t)row * L_;
    const float* lvrow  = logvar + (size_t)row * L_;
    const float* epsrow = eps + (size_t)row * L_;
    float* zw  = zs + w * L_;
    float* h3w = h3s + w * L_;
    float* h4w = h4s + w * L_;

    float yp = 0.f;
    for (int o = lane; o < L_; o += 32) {
        float m_ = murow[o];
        zw[o] = m_ + epsrow[o] * expf(0.5f * lvrow[o]);
        yp += m_ * fcy_w[o];
    }
#pragma unroll
    for (int off = 16; off; off >>= 1) yp += __shfl_xor_sync(0xffffffffu, yp, off);
    if (lane == 0) y[row] = yp + fcy_b[0];
    __syncwarp();

    for (int o = lane; o < L_; o += 32) {
        float sacc = sb3[o];
        const float* wr = sW3 + o * 69;
#pragma unroll 4
        for (int d = 0; d < L_; d++) sacc += zw[d] * wr[d];
        h3w[o] = sacc;                  // branch 0: NO sigmoid
    }
    __syncwarp();
    for (int o = lane; o < L_; o += 32) {
        float sacc = sb4[o];
        const float* wr = sW4 + o * 69;
#pragma unroll 4
        for (int d = 0; d < L_; d++) sacc += h3w[d] * wr[d];
        h4w[o] = 1.0f / (1.0f + expf(-sacc));
    }
    __syncwarp();
    for (int o = lane; o < L_; o += 32) {
        float sacc = sb5[o];
        const float* wr = sW5 + o * 69;
#pragma unroll 4
        for (int d = 0; d < L_; d++) sacc += h4w[d] * wr[d];
        h51[(size_t)row * L_ + o] = sacc;
    }
}

// ============================ launch ============================
extern "C" void kernel_launch(void* const* d_in, const int* in_sizes, int n_in,
                              void* d_out, int out_size)
{
    const float* x      = (const float*)d_in[0];
    const float* eps    = (const float*)d_in[1];
    const float* fc11_w = (const float*)d_in[2];
    const float* fc11_b = (const float*)d_in[3];
    const float* fc12_w = (const float*)d_in[4];
    const float* fc12_b = (const float*)d_in[5];
    const float* fc21_w = (const float*)d_in[6];
    const float* fc21_b = (const float*)d_in[7];
    const float* fc22_w = (const float*)d_in[8];
    const float* fc22_b = (const float*)d_in[9];
    const float* W3     = (const float*)d_in[10];
    const float* b3     = (const float*)d_in[11];
    const float* W4     = (const float*)d_in[12];
    const float* b4     = (const float*)d_in[13];
    const float* W5     = (const float*)d_in[14];
    const float* b5     = (const float*)d_in[15];
    const float* fc6_w  = (const float*)d_in[16];
    const float* fc6_b  = (const float*)d_in[17];
    const float* fcy_w  = (const float*)d_in[18];
    const float* fcy_b  = (const float*)d_in[19];

    float* out   = (float*)d_out;
    float* recon = out;
    float* mu    = out + (size_t)B_ * D_;
    float* lv    = mu + (size_t)B_ * L_;
    float* y     = lv + (size_t)B_ * L_;

    float* hbuf; cudaGetSymbolAddress((void**)&hbuf, g_h);
    float* h51;  cudaGetSymbolAddress((void**)&h51, g_h51);
    float* x32;  cudaGetSymbolAddress((void**)&x32, g_x32);
    float* w6;   cudaGetSymbolAddress((void**)&w6,  g_w6);
    float* w1;   cudaGetSymbolAddress((void**)&w1,  g_w1);
    float* w2;   cudaGetSymbolAddress((void**)&w2,  g_w2);
    float* b1;   cudaGetSymbolAddress((void**)&b1,  g_b1);

    // pre-pass: tf32-round GEMM operands (HBM-bound, ~50us total)
    const int CT = 256, CB = 1024;
    round_tf32_v4<<<CB, CT>>>((const float4*)x,      (float4*)x32, (B_ * D_) / 4);
    round_tf32_v4<<<CB, CT>>>((const float4*)fc11_w, (float4*)w1,                     (E_ * D_) / 4);
    round_tf32_v4<<<CB, CT>>>((const float4*)fc12_w, (float4*)(w1 + (size_t)E_ * D_), (E_ * D_) / 4);
    round_tf32_v4<<<CB, CT>>>((const float4*)fc21_w, (float4*)w2,                     (L_ * E_) / 4);
    round_tf32_v4<<<CB, CT>>>((const float4*)fc22_w, (float4*)(w2 + (size_t)L_ * E_), (L_ * E_) / 4);
    round_tf32_v4<<<CB, CT>>>((const float4*)fc6_w,  (float4*)w6, (D_ * D_) / 4);
    cudaMemcpyAsync(b1,      fc11_b, E_ * sizeof(float), cudaMemcpyDeviceToDevice);
    cudaMemcpyAsync(b1 + E_, fc12_b, E_ * sizeof(float), cudaMemcpyDeviceToDevice);

    const size_t smemEnc  = (size_t)6 * STAGE_U32 * 4;                 // 110592
    const size_t smemRec  = (size_t)(128 * L_ + 3 * STAGE_U32) * 4;    // 90112
    const size_t smemHead = (size_t)(2 * BM * KPAD + 2 * BN * KPAD) * 4;
    const size_t smemMid  = (size_t)(3 * L_ * 69 + 3 * L_ + 3 * 8 * L_) * 4;

    cudaFuncSetAttribute(gemm_ms<0>, cudaFuncAttributeMaxDynamicSharedMemorySize, (int)smemEnc);
    cudaFuncSetAttribute(gemm_ms<2>, cudaFuncAttributeMaxDynamicSharedMemorySize, (int)smemRec);
    cudaFuncSetAttribute(gemm_head,  cudaFuncAttributeMaxDynamicSharedMemorySize, (int)smemHead);
    cudaFuncSetAttribute(mid_kernel, cudaFuncAttributeMaxDynamicSharedMemorySize, (int)smemMid);

    // 1) hbuf = round(relu(x @ [fc11|fc12]^T + b))   [4096 x 2048]
    gemm_ms<0><<<dim3(2 * E_ / BN, B_ / BM), THREADS, smemEnc>>>(
        x32, D_, w1, b1, nullptr, hbuf, 2 * E_, 2 * E_, D_, 2 * E_);

    // 2) mu / logvar heads  [4096 x 68], z-batched
    gemm_head<<<dim3(1, B_ / BM, 2), THREADS, smemHead>>>(
        hbuf, w2, fc21_b, fc22_b, mu, B_ * L_);

    // 3) reparam + y + decoder branch 0 -> h51
    mid_kernel<<<B_ / 8, 256, smemMid>>>(
        mu, lv, eps, W3, b3, W4, b4, W5, b5, fcy_w, fcy_b, h51, y);

    // 4) recon = sigmoid(outer(h51) @ fc6_w^T + b)  [4096 x 4624]
    gemm_ms<2><<<dim3((D_ + BN - 1) / BN, B_ / BM), THREADS, smemRec>>>(
        nullptr, 0, w6, fc6_b, h51, recon, D_, D_, D_, D_);
}

// round 6
// speedup vs baseline: 1.4534x; 1.4534x over previous
#include <cuda_runtime.h>
#include <cuda_fp16.h>
#include <cstdint>

// Problem dims
#define B_  4096
#define D_  4624
#define L_  68
#define E_  1024

// GEMM tiling — fp16 mma.m16n8k16 path (fp16 mantissa == tf32 mantissa, 2x rate,
// half the smem crossbar bytes). tcgen05 unavailable (harness targets compute_103).
#define BM 128
#define BN 128
#define BK 32              // k-elements per tile
#define KPADH 20           // smem row stride in u32 (16 data u32 + 4 pad) — conflict-free
#define STAGEH_U32 (128 * KPADH)   // 2560 u32 = 10240 B per operand stage
#define THREADS 256

// ---- static scratch (no cudaMalloc allowed) ----
__device__ __half g_x16[(size_t)B_ * D_];        // x, fp16
__device__ __half g_h16[(size_t)B_ * 2 * E_];    // relu(x@fc11^T)|relu(x@fc12^T), fp16
__device__ __half g_w1h[(size_t)2 * E_ * D_];    // fc11_w|fc12_w concat, fp16
__device__ __half g_w2h[(size_t)2 * L_ * E_];    // fc21_w|fc22_w concat, fp16
__device__ __half g_w6h[(size_t)D_ * D_];        // fc6_w, fp16
__device__ float  g_h51[(size_t)B_ * L_];        // decoder branch-0 output (f32)
__device__ float  g_b1 [2 * E_];                 // fc11_b|fc12_b concat (f32)

// ============================ helpers ============================
__device__ __forceinline__ void mma_f16(float* c, uint32_t a0, uint32_t a1,
                                        uint32_t a2, uint32_t a3,
                                        uint32_t b0, uint32_t b1) {
    asm volatile(
        "mma.sync.aligned.m16n8k16.row.col.f32.f16.f16.f32 "
        "{%0,%1,%2,%3}, {%4,%5,%6,%7}, {%8,%9}, {%0,%1,%2,%3};\n"
        : "+f"(c[0]), "+f"(c[1]), "+f"(c[2]), "+f"(c[3])
        : "r"(a0), "r"(a1), "r"(a2), "r"(a3), "r"(b0), "r"(b1));
}

__device__ __forceinline__ void cp_async16(void* sptr, const void* gptr, int src_size) {
    uint32_t s = (uint32_t)__cvta_generic_to_shared(sptr);
    asm volatile("cp.async.cg.shared.global [%0], [%1], 16, %2;\n"
                 :: "r"(s), "l"(gptr), "r"(src_size));
}
__device__ __forceinline__ void cp_commit() { asm volatile("cp.async.commit_group;\n"); }
template <int N>
__device__ __forceinline__ void cp_wait() { asm volatile("cp.async.wait_group %0;\n" :: "n"(N)); }

__device__ __forceinline__ uint32_t pack_h2(float a, float b) {
    __half2 h = __floats2half2_rn(a, b);
    return *reinterpret_cast<uint32_t*>(&h);
}

// ============================ pre-pass: f32 -> f16 ============================
__global__ void f32_to_f16_v4(const float4* __restrict__ in, uint2* __restrict__ out, int n4) {
    int i = blockIdx.x * blockDim.x + threadIdx.x;
    int stride = gridDim.x * blockDim.x;
    for (; i < n4; i += stride) {
        float4 v = in[i];
        out[i] = make_uint2(pack_h2(v.x, v.y), pack_h2(v.z, v.w));
    }
}

// ============================ main GEMMs (fp16, 2-stage cp.async) ============================
// MODE 0: hbuf16 = fp16(relu(A16 @ W16^T + bias))   (encoder fc11|fc12 concat)
// MODE 2: C = sigmoid(outer(h51) @ W16^T + bias)    (recon; A staged fp16 in smem)
template <int MODE>
__global__ void __launch_bounds__(THREADS, 2)
gemm_f16(const __half* __restrict__ A, int lda,
         const __half* __restrict__ W, const float* __restrict__ bias,
         const float* __restrict__ h51,
         void* __restrict__ Cout, int ldc, int N, int K, int Nw)
{
    extern __shared__ unsigned char smem_raw[];
    uint32_t* sm = reinterpret_cast<uint32_t*>(smem_raw);

    // MODE 0: As = sm[0..2*STAGE), Bs = sm[2*STAGE..4*STAGE)
    // MODE 2: h51s = sm[0..128*68) f32, then As (2 stages), Bs (2 stages)
    float*    h51s = reinterpret_cast<float*>(sm);
    uint32_t* As   = (MODE == 2) ? (sm + 128 * L_) : sm;
    uint32_t* Bs   = As + 2 * STAGEH_U32;

    const int tid  = threadIdx.x;
    const int lane = tid & 31;
    const int warp = tid >> 5;
    const int wm   = warp & 3;          // 4 warps along M
    const int wn   = warp >> 2;         // 2 warps along N
    const int grp  = lane >> 2;
    const int tig  = lane & 3;
    const int m0   = blockIdx.y * BM;
    const int n0   = blockIdx.x * BN;
    const int kt   = (K + BK - 1) / BK;

    if (MODE == 2) {
        for (int idx = tid; idx < BM * L_; idx += THREADS)
            h51s[idx] = h51[(size_t)m0 * L_ + idx];
        __syncthreads();
    }

    auto prefetch = [&](int t) {
        const int buf = t & 1;
        const int k0  = t * BK;
        uint32_t* Ab = As + buf * STAGEH_U32;
        uint32_t* Bb = Bs + buf * STAGEH_U32;
        if (MODE == 0) {
            // A: 128 rows x 32 halves = 512 x 16B chunks
#pragma unroll
            for (int i = 0; i < 2; i++) {
                int q = tid + i * 256;
                int r = q >> 2, ch = q & 3;
                int k = k0 + ch * 8;                    // K % 8 == 0 -> all-or-nothing
                cp_async16(Ab + r * KPADH + ch * 4,
                           A + (size_t)(m0 + r) * lda + k, (k < K) ? 16 : 0);
            }
        } else {
            // A: outer-product synth, fp16, STS.128 (2 per thread)
#pragma unroll
            for (int i = 0; i < 2; i++) {
                int q = tid + i * 256;
                int r = q >> 2, ch = q & 3;
                int kb = k0 + ch * 8;
                const float* hr = h51s + r * L_;
                uint32_t v[4];
#pragma unroll
                for (int p = 0; p < 4; p++) {
                    int ka = kb + 2 * p, kb2 = ka + 1;
                    float f0 = 0.f, f1 = 0.f;
                    if (ka < K) { int ii = ka / L_; f0 = hr[ii] * hr[ka - ii * L_]; }
                    if (kb2 < K) { int ii = kb2 / L_; f1 = hr[ii] * hr[kb2 - ii * L_]; }
                    v[p] = pack_h2(f0, f1);
                }
                uint32_t daddr = (uint32_t)__cvta_generic_to_shared(Ab + r * KPADH + ch * 4);
                asm volatile("st.shared.v4.b32 [%0], {%1,%2,%3,%4};"
                             :: "r"(daddr), "r"(v[0]), "r"(v[1]), "r"(v[2]), "r"(v[3])
                             : "memory");
            }
        }
        // B: weights [Nw, K] row-major (NT gemm), fp16
#pragma unroll
        for (int i = 0; i < 2; i++) {
            int q = tid + i * 256;
            int r = q >> 2, ch = q & 3;
            int k = k0 + ch * 8;
            int row = n0 + r;
            const __half* src = W + (size_t)(row < Nw ? row : 0) * K + k;
            cp_async16(Bb + r * KPADH + ch * 4, src, (row < Nw && k < K) ? 16 : 0);
        }
        cp_commit();
    };

    float acc[2][8][4] = {};
    const int aBase = wm * 32 + grp;
    const int bBase = wn * 64 + grp;

    auto compute = [&](int buf) {
        const uint32_t* Ab = As + buf * STAGEH_U32;
        const uint32_t* Bb = Bs + buf * STAGEH_U32;
#pragma unroll
        for (int kk = 0; kk < 2; kk++) {              // two k16 steps per k32 tile
            int u = kk * 8 + tig;                     // u32 index within row
            uint32_t a[2][4];
#pragma unroll
            for (int mt = 0; mt < 2; mt++) {
                int r = aBase + mt * 16;
                a[mt][0] = Ab[r * KPADH + u];
                a[mt][1] = Ab[(r + 8) * KPADH + u];
                a[mt][2] = Ab[r * KPADH + u + 4];
                a[mt][3] = Ab[(r + 8) * KPADH + u + 4];
            }
#pragma unroll
            for (int nt = 0; nt < 8; nt++) {
                int c = bBase + nt * 8;
                uint32_t b0 = Bb[c * KPADH + u];
                uint32_t b1 = Bb[c * KPADH + u + 4];
#pragma unroll
                for (int mt = 0; mt < 2; mt++)
                    mma_f16(acc[mt][nt], a[mt][0], a[mt][1], a[mt][2], a[mt][3], b0, b1);
            }
        }
    };

    prefetch(0);
    for (int t = 0; t < kt; t++) {
        if (t + 1 < kt) { prefetch(t + 1); cp_wait<1>(); }
        else            { cp_wait<0>(); }
        __syncthreads();
        compute(t & 1);
        __syncthreads();
    }

    // Epilogue
#pragma unroll
    for (int mt = 0; mt < 2; mt++) {
        int row = m0 + wm * 32 + mt * 16 + grp;
#pragma unroll
        for (int nt = 0; nt < 8; nt++) {
            int ncl = wn * 64 + nt * 8 + tig * 2;     // column pair (ncl, ncl+1)
#pragma unroll
            for (int half = 0; half < 2; half++) {    // half=0 -> row, half=1 -> row+8
                int r   = row + half * 8;
                int col = n0 + ncl;
                float v0 = acc[mt][nt][half * 2 + 0] + bias[col];
                float v1 = acc[mt][nt][half * 2 + 1] + ((col + 1 < N) ? bias[col + 1] : 0.f);
                if (MODE == 0) {
                    v0 = v0 > 0.f ? v0 : 0.f;
                    v1 = v1 > 0.f ? v1 : 0.f;
                    // store fp16 pair (rounding == tf32 mantissa)
                    *reinterpret_cast<uint32_t*>(
                        (__half*)Cout + (size_t)r * ldc + col) = pack_h2(v0, v1);
                } else {
                    float* C = (float*)Cout;
                    if (col < N)     C[(size_t)r * ldc + col]     = 1.0f / (1.0f + __expf(-v0));
                    if (col + 1 < N) C[(size_t)r * ldc + col + 1] = 1.0f / (1.0f + __expf(-v1));
                }
            }
        }
    }
}

// ============================ head GEMM (mu / logvar), fp16 ============================
__global__ void __launch_bounds__(THREADS, 2)
gemm_head(const __half* __restrict__ Abase, const __half* __restrict__ Wbase,
          const float* __restrict__ bias0, const float* __restrict__ bias1,
          float* __restrict__ Cbase, int batchStrideC)
{
    extern __shared__ unsigned char smem_raw[];
    uint32_t* As = reinterpret_cast<uint32_t*>(smem_raw);
    uint32_t* Bs = As + 2 * STAGEH_U32;

    const int tid = threadIdx.x;
    const int m0  = blockIdx.y * BM;
    const int N = L_, K = E_;

    const int z = blockIdx.z;
    const __half* A    = Abase + (size_t)z * E_;     // column offset into g_h16
    const __half* W    = Wbase + (size_t)z * L_ * E_;
    const float* bias  = z ? bias1 : bias0;
    float* C           = Cbase + (size_t)z * batchStrideC;

    auto prefetch = [&](int t) {
        const int buf = t & 1;
        const int k0  = t * BK;
        uint32_t* Ab = As + buf * STAGEH_U32;
        uint32_t* Bb = Bs + buf * STAGEH_U32;
#pragma unroll
        for (int i = 0; i < 2; i++) {
            int q = tid + i * 256;
            int r = q >> 2, ch = q & 3;
            int k = k0 + ch * 8;
            cp_async16(Ab + r * KPADH + ch * 4,
                       A + (size_t)(m0 + r) * (2 * E_) + k, 16);
            const __half* src = W + (size_t)(r < N ? r : 0) * K + k;
            cp_async16(Bb + r * KPADH + ch * 4, src, (r < N) ? 16 : 0);
        }
        cp_commit();
    };

    float acc[2][8][4] = {};
    const int lane = tid & 31;
    const int warp = tid >> 5;
    const int wm = warp & 3;
    const int wn = warp >> 2;
    const int grp = lane >> 2;
    const int tig = lane & 3;
    const int aBase = wm * 32 + grp;
    const int bBase = wn * 64 + grp;

    auto compute = [&](int buf) {
        const uint32_t* Ab = As + buf * STAGEH_U32;
        const uint32_t* Bb = Bs + buf * STAGEH_U32;
#pragma unroll
        for (int kk = 0; kk < 2; kk++) {
            int u = kk * 8 + tig;
            uint32_t a[2][4];
#pragma unroll
            for (int mt = 0; mt < 2; mt++) {
                int r = aBase + mt * 16;
                a[mt][0] = Ab[r * KPADH + u];
                a[mt][1] = Ab[(r + 8) * KPADH + u];
                a[mt][2] = Ab[r * KPADH + u + 4];
                a[mt][3] = Ab[(r + 8) * KPADH + u + 4];
            }
#pragma unroll
            for (int nt = 0; nt < 8; nt++) {
                int c = bBase + nt * 8;
                uint32_t b0 = Bb[c * KPADH + u];
                uint32_t b1 = Bb[c * KPADH + u + 4];
#pragma unroll
                for (int mt = 0; mt < 2; mt++)
                    mma_f16(acc[mt][nt], a[mt][0], a[mt][1], a[mt][2], a[mt][3], b0, b1);
            }
        }
    };

    const int kt = K / BK;
    prefetch(0);
    for (int t = 0; t < kt; t++) {
        if (t + 1 < kt) { prefetch(t + 1); cp_wait<1>(); }
        else            { cp_wait<0>(); }
        __syncthreads();
        compute(t & 1);
        __syncthreads();
    }

#pragma unroll
    for (int mt = 0; mt < 2; mt++) {
        int row = m0 + wm * 32 + mt * 16 + grp;
#pragma unroll
        for (int nt = 0; nt < 8; nt++) {
            int ncl = wn * 64 + nt * 8 + tig * 2;
#pragma unroll
            for (int e = 0; e < 4; e++) {
                int r   = row + ((e >= 2) ? 8 : 0);
                int col = ncl + (e & 1);
                if (col < N)
                    C[(size_t)r * N + col] = acc[mt][nt][e] + bias[col];
            }
        }
    }
}

// ============================ mid kernel ============================
// z = mu + eps*exp(0.5*logvar); y = mu@fcy^T+b; decoder branch 0 only (others dead)
__global__ void __launch_bounds__(256, 1)
mid_kernel(const float* __restrict__ mu, const float* __restrict__ logvar,
           const float* __restrict__ eps,
           const float* __restrict__ W3, const float* __restrict__ b3,
           const float* __restrict__ W4, const float* __restrict__ b4,
           const float* __restrict__ W5, const float* __restrict__ b5,
           const float* __restrict__ fcy_w, const float* __restrict__ fcy_b,
           float* __restrict__ h51, float* __restrict__ y)
{
    extern __shared__ unsigned char smem_raw[];
    float* s   = reinterpret_cast<float*>(smem_raw);
    float* sW3 = s;
    float* sW4 = sW3 + L_ * 69;
    float* sW5 = sW4 + L_ * 69;
    float* sb3 = sW5 + L_ * 69;
    float* sb4 = sb3 + L_;
    float* sb5 = sb4 + L_;
    float* zs  = sb5 + L_;
    float* h3s = zs + 8 * L_;
    float* h4s = h3s + 8 * L_;

    const int tid = threadIdx.x;
    for (int idx = tid; idx < L_ * L_; idx += 256) {
        int o = idx / L_, d = idx - o * L_;
        sW3[o * 69 + d] = W3[idx];
        sW4[o * 69 + d] = W4[idx];
        sW5[o * 69 + d] = W5[idx];
    }
    for (int idx = tid; idx < L_; idx += 256) {
        sb3[idx] = b3[idx]; sb4[idx] = b4[idx]; sb5[idx] = b5[idx];
    }
    __syncthreads();

    const int lane = tid & 31, w = tid >> 5;
    const int row = blockIdx.x * 8 + w;
    const float* murow  = mu + (size_t)row * L_;
    const float* lvrow  = logvar + (size_t)row * L_;
    const float* epsrow = eps + (size_t)row * L_;
    float* zw  = zs + w * L_;
    float* h3w = h3s + w * L_;
    float* h4w = h4s + w * L_;

    float yp = 0.f;
    for (int o = lane; o < L_; o += 32) {
        float m_ = murow[o];
        zw[o] = m_ + epsrow[o] * expf(0.5f * lvrow[o]);
        yp += m_ * fcy_w[o];
    }
#pragma unroll
    for (int off = 16; off; off >>= 1) yp += __shfl_xor_sync(0xffffffffu, yp, off);
    if (lane == 0) y[row] = yp + fcy_b[0];
    __syncwarp();

    for (int o = lane; o < L_; o += 32) {
        float sacc = sb3[o];
        const float* wr = sW3 + o * 69;
#pragma unroll 4
        for (int d = 0; d < L_; d++) sacc += zw[d] * wr[d];
        h3w[o] = sacc;                  // branch 0: NO sigmoid
    }
    __syncwarp();
    for (int o = lane; o < L_; o += 32) {
        float sacc = sb4[o];
        const float* wr = sW4 + o * 69;
#pragma unroll 4
        for (int d = 0; d < L_; d++) sacc += h3w[d] * wr[d];
        h4w[o] = 1.0f / (1.0f + expf(-sacc));
    }
    __syncwarp();
    for (int o = lane; o < L_; o += 32) {
        float sacc = sb5[o];
        const float* wr = sW5 + o * 69;
#pragma unroll 4
        for (int d = 0; d < L_; d++) sacc += h4w[d] * wr[d];
        h51[(size_t)row * L_ + o] = sacc;
    }
}

// ============================ launch ============================
extern "C" void kernel_launch(void* const* d_in, const int* in_sizes, int n_in,
                              void* d_out, int out_size)
{
    const float* x      = (const float*)d_in[0];
    const float* eps    = (const float*)d_in[1];
    const float* fc11_w = (const float*)d_in[2];
    const float* fc11_b = (const float*)d_in[3];
    const float* fc12_w = (const float*)d_in[4];
    const float* fc12_b = (const float*)d_in[5];
    const float* fc21_w = (const float*)d_in[6];
    const float* fc21_b = (const float*)d_in[7];
    const float* fc22_w = (const float*)d_in[8];
    const float* fc22_b = (const float*)d_in[9];
    const float* W3     = (const float*)d_in[10];
    const float* b3     = (const float*)d_in[11];
    const float* W4     = (const float*)d_in[12];
    const float* b4     = (const float*)d_in[13];
    const float* W5     = (const float*)d_in[14];
    const float* b5     = (const float*)d_in[15];
    const float* fc6_w  = (const float*)d_in[16];
    const float* fc6_b  = (const float*)d_in[17];
    const float* fcy_w  = (const float*)d_in[18];
    const float* fcy_b  = (const float*)d_in[19];

    float* out   = (float*)d_out;
    float* recon = out;
    float* mu    = out + (size_t)B_ * D_;
    float* lv    = mu + (size_t)B_ * L_;
    float* y     = lv + (size_t)B_ * L_;

    __half* x16;  cudaGetSymbolAddress((void**)&x16, g_x16);
    __half* h16;  cudaGetSymbolAddress((void**)&h16, g_h16);
    __half* w1h;  cudaGetSymbolAddress((void**)&w1h, g_w1h);
    __half* w2h;  cudaGetSymbolAddress((void**)&w2h, g_w2h);
    __half* w6h;  cudaGetSymbolAddress((void**)&w6h, g_w6h);
    float*  h51;  cudaGetSymbolAddress((void**)&h51, g_h51);
    float*  b1;   cudaGetSymbolAddress((void**)&b1,  g_b1);

    // pre-pass: convert GEMM operands to fp16 (HBM-bound, ~40us total)
    const int CT = 256, CB = 1024;
    f32_to_f16_v4<<<CB, CT>>>((const float4*)x,      (uint2*)x16, (B_ * D_) / 4);
    f32_to_f16_v4<<<CB, CT>>>((const float4*)fc11_w, (uint2*)w1h,                     (E_ * D_) / 4);
    f32_to_f16_v4<<<CB, CT>>>((const float4*)fc12_w, (uint2*)(w1h + (size_t)E_ * D_), (E_ * D_) / 4);
    f32_to_f16_v4<<<CB, CT>>>((const float4*)fc21_w, (uint2*)w2h,                     (L_ * E_) / 4);
    f32_to_f16_v4<<<CB, CT>>>((const float4*)fc22_w, (uint2*)(w2h + (size_t)L_ * E_), (L_ * E_) / 4);
    f32_to_f16_v4<<<CB, CT>>>((const float4*)fc6_w,  (uint2*)w6h, (D_ * D_) / 4);
    cudaMemcpyAsync(b1,      fc11_b, E_ * sizeof(float), cudaMemcpyDeviceToDevice);
    cudaMemcpyAsync(b1 + E_, fc12_b, E_ * sizeof(float), cudaMemcpyDeviceToDevice);

    const size_t smemEnc  = (size_t)4 * STAGEH_U32 * 4;                 // 40960
    const size_t smemRec  = (size_t)(128 * L_ + 4 * STAGEH_U32) * 4;    // 75776
    const size_t smemHead = (size_t)4 * STAGEH_U32 * 4;                 // 40960
    const size_t smemMid  = (size_t)(3 * L_ * 69 + 3 * L_ + 3 * 8 * L_) * 4;

    cudaFuncSetAttribute(gemm_f16<0>, cudaFuncAttributeMaxDynamicSharedMemorySize, (int)smemEnc);
    cudaFuncSetAttribute(gemm_f16<2>, cudaFuncAttributeMaxDynamicSharedMemorySize, (int)smemRec);
    cudaFuncSetAttribute(gemm_head,   cudaFuncAttributeMaxDynamicSharedMemorySize, (int)smemHead);
    cudaFuncSetAttribute(mid_kernel,  cudaFuncAttributeMaxDynamicSharedMemorySize, (int)smemMid);

    // 1) h16 = fp16(relu(x @ [fc11|fc12]^T + b))   [4096 x 2048]
    gemm_f16<0><<<dim3(2 * E_ / BN, B_ / BM), THREADS, smemEnc>>>(
        x16, D_, w1h, b1, nullptr, h16, 2 * E_, 2 * E_, D_, 2 * E_);

    // 2) mu / logvar heads  [4096 x 68], z-batched
    gemm_head<<<dim3(1, B_ / BM, 2), THREADS, smemHead>>>(
        h16, w2h, fc21_b, fc22_b, mu, B_ * L_);

    // 3) reparam + y + decoder branch 0 -> h51
    mid_kernel<<<B_ / 8, 256, smemMid>>>(
        mu, lv, eps, W3, b3, W4, b4, W5, b5, fcy_w, fcy_b, h51, y);

    // 4) recon = sigmoid(outer(h51) @ fc6_w^T + b)  [4096 x 4624]
    gemm_f16<2><<<dim3((D_ + BN - 1) / BN, B_ / BM), THREADS, smemRec>>>(
        nullptr, 0, w6h, fc6_b, h51, recon, D_, D_, D_, D_);
}

// round 7
// speedup vs baseline: 1.6571x; 1.1401x over previous
#include <cuda_runtime.h>
#include <cuda_fp16.h>
#include <cstdint>

// Problem dims
#define B_  4096
#define D_  4624
#define L_  68
#define E_  1024

// fp16 mma.m16n8k16 + ldmatrix path (tcgen05 unavailable: harness targets compute_103)
#define BM 128
#define BN 128
#define BK 32              // k-elements per tile
#define KPADH 20           // smem row stride in u32 (16 data + 4 pad) — conflict-free for
                           // both cp.async stores and ldmatrix row-phases
#define STAGEH_U32 (128 * KPADH)       // 2560 u32 = 10240 B per operand stage
#define STAGE_BYTES (STAGEH_U32 * 4)
#define THREADS 256

// ---- static scratch (no cudaMalloc allowed) ----
__device__ __half g_x16[(size_t)B_ * D_];        // x, fp16
__device__ __half g_h16[(size_t)B_ * 2 * E_];    // relu(x@fc11^T)|relu(x@fc12^T), fp16
__device__ __half g_w1h[(size_t)2 * E_ * D_];    // fc11_w|fc12_w concat, fp16
__device__ __half g_w2h[(size_t)2 * L_ * E_];    // fc21_w|fc22_w concat, fp16
__device__ __half g_w6h[(size_t)D_ * D_];        // fc6_w, fp16
__device__ float  g_h51[(size_t)B_ * L_];        // decoder branch-0 output (f32)
__device__ float  g_b1 [2 * E_];                 // fc11_b|fc12_b concat (f32)

// ============================ helpers ============================
__device__ __forceinline__ void mma_f16(float* c, uint32_t a0, uint32_t a1,
                                        uint32_t a2, uint32_t a3,
                                        uint32_t b0, uint32_t b1) {
    asm volatile(
        "mma.sync.aligned.m16n8k16.row.col.f32.f16.f16.f32 "
        "{%0,%1,%2,%3}, {%4,%5,%6,%7}, {%8,%9}, {%0,%1,%2,%3};\n"
        : "+f"(c[0]), "+f"(c[1]), "+f"(c[2]), "+f"(c[3])
        : "r"(a0), "r"(a1), "r"(a2), "r"(a3), "r"(b0), "r"(b1));
}

__device__ __forceinline__ void ldmatrix_x4(uint32_t& d0, uint32_t& d1,
                                            uint32_t& d2, uint32_t& d3, uint32_t addr) {
    asm volatile("ldmatrix.sync.aligned.m8n8.x4.shared.b16 {%0,%1,%2,%3}, [%4];"
                 : "=r"(d0), "=r"(d1), "=r"(d2), "=r"(d3) : "r"(addr));
}

__device__ __forceinline__ void cp_async16(void* sptr, const void* gptr, int src_size) {
    uint32_t s = (uint32_t)__cvta_generic_to_shared(sptr);
    asm volatile("cp.async.cg.shared.global [%0], [%1], 16, %2;\n"
                 :: "r"(s), "l"(gptr), "r"(src_size));
}
__device__ __forceinline__ void cp_commit() { asm volatile("cp.async.commit_group;\n"); }
template <int N>
__device__ __forceinline__ void cp_wait() { asm volatile("cp.async.wait_group %0;\n" :: "n"(N)); }

__device__ __forceinline__ uint32_t pack_h2(float a, float b) {
    __half2 h = __floats2half2_rn(a, b);
    return *reinterpret_cast<uint32_t*>(&h);
}

// ============================ pre-pass: f32 -> f16 ============================
__global__ void f32_to_f16_v4(const float4* __restrict__ in, uint2* __restrict__ out, int n4) {
    int i = blockIdx.x * blockDim.x + threadIdx.x;
    int stride = gridDim.x * blockDim.x;
    for (; i < n4; i += stride) {
        float4 v = in[i];
        out[i] = make_uint2(pack_h2(v.x, v.y), pack_h2(v.z, v.w));
    }
}

// ============================ main GEMMs (fp16, ldmatrix, 3-stage) ============================
// MODE 0: h16 = fp16(relu(A16 @ W16^T + bias))     (encoder fc11|fc12 concat)
// MODE 2: C = sigmoid(outer(h51) @ W16^T + bias)   (recon; A staged fp16 in smem)
template <int MODE>
__global__ void __launch_bounds__(THREADS, 2)
gemm_f16(const __half* __restrict__ A, int lda,
         const __half* __restrict__ W, const float* __restrict__ bias,
         const float* __restrict__ h51,
         void* __restrict__ Cout, int ldc, int N, int K, int Nw)
{
    extern __shared__ unsigned char smem_raw[];
    uint32_t* sm = reinterpret_cast<uint32_t*>(smem_raw);

    float*    h51s = reinterpret_cast<float*>(sm);
    uint32_t* As   = (MODE == 2) ? (sm + 128 * L_) : sm;     // 3 stages
    uint32_t* Bs   = As + 3 * STAGEH_U32;                    // 3 stages

    const int tid  = threadIdx.x;
    const int lane = tid & 31;
    const int warp = tid >> 5;
    const int wm   = warp & 3;          // 4 warps along M (32 rows each)
    const int wn   = warp >> 2;         // 2 warps along N (64 cols each)
    const int grp  = lane >> 2;
    const int tig  = lane & 3;
    const int m0   = blockIdx.y * BM;
    const int n0   = blockIdx.x * BN;
    const int kt   = (K + BK - 1) / BK;

    if (MODE == 2) {
        for (int idx = tid; idx < BM * L_; idx += THREADS)
            h51s[idx] = h51[(size_t)m0 * L_ + idx];
        __syncthreads();
    }

    const uint32_t As_b = (uint32_t)__cvta_generic_to_shared(As);
    const uint32_t Bs_b = (uint32_t)__cvta_generic_to_shared(Bs);

    // per-lane ldmatrix source coordinates
    const int aRow  = wm * 32 + ((lane >> 3) & 1) * 8 + (lane & 7);  // + mt*16
    const int aColB = (lane >> 4) * 16;                              // k-half byte offset
    const int bRow  = wn * 64 + (lane >> 4) * 8 + (lane & 7);        // + nt16*16
    const int bColB = ((lane >> 3) & 1) * 16;

    auto prefetch = [&](int t) {
        const int s  = t % 3;
        const int k0 = t * BK;
        uint32_t* Ab = As + s * STAGEH_U32;
        uint32_t* Bb = Bs + s * STAGEH_U32;
        if (MODE == 0) {
#pragma unroll
            for (int i = 0; i < 2; i++) {
                int q = tid + i * 256;
                int r = q >> 2, ch = q & 3;
                int k = k0 + ch * 8;
                cp_async16(Ab + r * KPADH + ch * 4,
                           A + (size_t)(m0 + r) * lda + k, (k < K) ? 16 : 0);
            }
        } else {
            // A: outer-product synth, fp16, STS.128
#pragma unroll
            for (int i = 0; i < 2; i++) {
                int q = tid + i * 256;
                int r = q >> 2, ch = q & 3;
                int kb = k0 + ch * 8;
                const float* hr = h51s + r * L_;
                uint32_t v[4];
#pragma unroll
                for (int p = 0; p < 4; p++) {
                    int ka = kb + 2 * p, k2 = ka + 1;
                    float f0 = 0.f, f1 = 0.f;
                    if (ka < K) { int ii = ka / L_; f0 = hr[ii] * hr[ka - ii * L_]; }
                    if (k2 < K) { int ii = k2 / L_; f1 = hr[ii] * hr[k2 - ii * L_]; }
                    v[p] = pack_h2(f0, f1);
                }
                uint32_t daddr = (uint32_t)__cvta_generic_to_shared(Ab + r * KPADH + ch * 4);
                asm volatile("st.shared.v4.b32 [%0], {%1,%2,%3,%4};"
                             :: "r"(daddr), "r"(v[0]), "r"(v[1]), "r"(v[2]), "r"(v[3])
                             : "memory");
            }
        }
        // B: weights [Nw, K] row-major (NT gemm), fp16
#pragma unroll
        for (int i = 0; i < 2; i++) {
            int q = tid + i * 256;
            int r = q >> 2, ch = q & 3;
            int k = k0 + ch * 8;
            int row = n0 + r;
            const __half* src = W + (size_t)(row < Nw ? row : 0) * K + k;
            cp_async16(Bb + r * KPADH + ch * 4, src, (row < Nw && k < K) ? 16 : 0);
        }
        cp_commit();
    };

    float acc[2][8][4] = {};

    auto compute = [&](int buf) {
        const uint32_t abase = As_b + buf * STAGE_BYTES;
        const uint32_t bbase = Bs_b + buf * STAGE_BYTES;
#pragma unroll
        for (int kk = 0; kk < 2; kk++) {              // two k16 steps per k32 tile
            const int kb = kk * 32;                   // byte offset of k16 step
            uint32_t a[2][4];
#pragma unroll
            for (int mt = 0; mt < 2; mt++)
                ldmatrix_x4(a[mt][0], a[mt][1], a[mt][2], a[mt][3],
                            abase + (uint32_t)(aRow + mt * 16) * (KPADH * 4) + kb + aColB);
#pragma unroll
            for (int nt16 = 0; nt16 < 4; nt16++) {
                uint32_t b0, b1, b2, b3;
                ldmatrix_x4(b0, b1, b2, b3,
                            bbase + (uint32_t)(bRow + nt16 * 16) * (KPADH * 4) + kb + bColB);
#pragma unroll
                for (int mt = 0; mt < 2; mt++) {
                    mma_f16(acc[mt][nt16 * 2 + 0], a[mt][0], a[mt][1], a[mt][2], a[mt][3], b0, b1);
                    mma_f16(acc[mt][nt16 * 2 + 1], a[mt][0], a[mt][1], a[mt][2], a[mt][3], b2, b3);
                }
            }
        }
    };

    // 3-stage pipeline, one __syncthreads per iteration
    prefetch(0);
    prefetch(1);
    for (int t = 0; t < kt; t++) {
        if (t < kt - 1) cp_wait<1>(); else cp_wait<0>();
        __syncthreads();
        if (t + 2 < kt) prefetch(t + 2);
        compute(t % 3);
    }

    // Epilogue
#pragma unroll
    for (int mt = 0; mt < 2; mt++) {
        int row = m0 + wm * 32 + mt * 16 + grp;
#pragma unroll
        for (int nt = 0; nt < 8; nt++) {
            int ncl = wn * 64 + nt * 8 + tig * 2;
#pragma unroll
            for (int half = 0; half < 2; half++) {
                int r   = row + half * 8;
                int col = n0 + ncl;
                float v0 = acc[mt][nt][half * 2 + 0] + bias[col];
                float v1 = acc[mt][nt][half * 2 + 1] + ((col + 1 < N) ? bias[col + 1] : 0.f);
                if (MODE == 0) {
                    v0 = v0 > 0.f ? v0 : 0.f;
                    v1 = v1 > 0.f ? v1 : 0.f;
                    *reinterpret_cast<uint32_t*>(
                        (__half*)Cout + (size_t)r * ldc + col) = pack_h2(v0, v1);
                } else {
                    float* C = (float*)Cout;
                    if (col < N)     C[(size_t)r * ldc + col]     = 1.0f / (1.0f + __expf(-v0));
                    if (col + 1 < N) C[(size_t)r * ldc + col + 1] = 1.0f / (1.0f + __expf(-v1));
                }
            }
        }
    }
}

// ============================ head GEMM (mu / logvar), fp16 ============================
__global__ void __launch_bounds__(THREADS, 2)
gemm_head(const __half* __restrict__ Abase, const __half* __restrict__ Wbase,
          const float* __restrict__ bias0, const float* __restrict__ bias1,
          float* __restrict__ Cbase, int batchStrideC)
{
    extern __shared__ unsigned char smem_raw[];
    uint32_t* As = reinterpret_cast<uint32_t*>(smem_raw);
    uint32_t* Bs = As + 2 * STAGEH_U32;

    const int tid = threadIdx.x;
    const int m0  = blockIdx.y * BM;
    const int N = L_, K = E_;

    const int z = blockIdx.z;
    const __half* A    = Abase + (size_t)z * E_;     // column offset into g_h16
    const __half* W    = Wbase + (size_t)z * L_ * E_;
    const float* bias  = z ? bias1 : bias0;
    float* C           = Cbase + (size_t)z * batchStrideC;

    const int lane = tid & 31;
    const int warp = tid >> 5;
    const int wm = warp & 3;
    const int wn = warp >> 2;
    const int grp = lane >> 2;
    const int tig = lane & 3;

    const uint32_t As_b = (uint32_t)__cvta_generic_to_shared(As);
    const uint32_t Bs_b = (uint32_t)__cvta_generic_to_shared(Bs);
    const int aRow  = wm * 32 + ((lane >> 3) & 1) * 8 + (lane & 7);
    const int aColB = (lane >> 4) * 16;
    const int bRow  = wn * 64 + (lane >> 4) * 8 + (lane & 7);
    const int bColB = ((lane >> 3) & 1) * 16;

    auto prefetch = [&](int t) {
        const int buf = t & 1;
        const int k0  = t * BK;
        uint32_t* Ab = As + buf * STAGEH_U32;
        uint32_t* Bb = Bs + buf * STAGEH_U32;
#pragma unroll
        for (int i = 0; i < 2; i++) {
            int q = tid + i * 256;
            int r = q >> 2, ch = q & 3;
            int k = k0 + ch * 8;
            cp_async16(Ab + r * KPADH + ch * 4,
                       A + (size_t)(m0 + r) * (2 * E_) + k, 16);
            const __half* src = W + (size_t)(r < N ? r : 0) * K + k;
            cp_async16(Bb + r * KPADH + ch * 4, src, (r < N) ? 16 : 0);
        }
        cp_commit();
    };

    float acc[2][8][4] = {};

    auto compute = [&](int buf) {
        const uint32_t abase = As_b + buf * STAGE_BYTES;
        const uint32_t bbase = Bs_b + buf * STAGE_BYTES;
#pragma unroll
        for (int kk = 0; kk < 2; kk++) {
            const int kb = kk * 32;
            uint32_t a[2][4];
#pragma unroll
            for (int mt = 0; mt < 2; mt++)
                ldmatrix_x4(a[mt][0], a[mt][1], a[mt][2], a[mt][3],
                            abase + (uint32_t)(aRow + mt * 16) * (KPADH * 4) + kb + aColB);
#pragma unroll
            for (int nt16 = 0; nt16 < 4; nt16++) {
                uint32_t b0, b1, b2, b3;
                ldmatrix_x4(b0, b1, b2, b3,
                            bbase + (uint32_t)(bRow + nt16 * 16) * (KPADH * 4) + kb + bColB);
#pragma unroll
                for (int mt = 0; mt < 2; mt++) {
                    mma_f16(acc[mt][nt16 * 2 + 0], a[mt][0], a[mt][1], a[mt][2], a[mt][3], b0, b1);
                    mma_f16(acc[mt][nt16 * 2 + 1], a[mt][0], a[mt][1], a[mt][2], a[mt][3], b2, b3);
                }
            }
        }
    };

    const int kt = K / BK;
    prefetch(0);
    for (int t = 0; t < kt; t++) {
        if (t + 1 < kt) { prefetch(t + 1); cp_wait<1>(); }
        else            { cp_wait<0>(); }
        __syncthreads();
        compute(t & 1);
        __syncthreads();
    }

#pragma unroll
    for (int mt = 0; mt < 2; mt++) {
        int row = m0 + wm * 32 + mt * 16 + grp;
#pragma unroll
        for (int nt = 0; nt < 8; nt++) {
            int ncl = wn * 64 + nt * 8 + tig * 2;
#pragma unroll
            for (int e = 0; e < 4; e++) {
                int r   = row + ((e >= 2) ? 8 : 0);
                int col = ncl + (e & 1);
                if (col < N)
                    C[(size_t)r * N + col] = acc[mt][nt][e] + bias[col];
            }
        }
    }
}

// ============================ mid kernel ============================
// z = mu + eps*exp(0.5*logvar); y = mu@fcy^T+b; decoder branch 0 only (others dead)
__global__ void __launch_bounds__(256, 1)
mid_kernel(const float* __restrict__ mu, const float* __restrict__ logvar,
           const float* __restrict__ eps,
           const float* __restrict__ W3, const float* __restrict__ b3,
           const float* __restrict__ W4, const float* __restrict__ b4,
           const float* __restrict__ W5, const float* __restrict__ b5,
           const float* __restrict__ fcy_w, const float* __restrict__ fcy_b,
           float* __restrict__ h51, float* __restrict__ y)
{
    extern __shared__ unsigned char smem_raw[];
    float* s   = reinterpret_cast<float*>(smem_raw);
    float* sW3 = s;
    float* sW4 = sW3 + L_ * 69;
    float* sW5 = sW4 + L_ * 69;
    float* sb3 = sW5 + L_ * 69;
    float* sb4 = sb3 + L_;
    float* sb5 = sb4 + L_;
    float* zs  = sb5 + L_;
    float* h3s = zs + 8 * L_;
    float* h4s = h3s + 8 * L_;

    const int tid = threadIdx.x;
    for (int idx = tid; idx < L_ * L_; idx += 256) {
        int o = idx / L_, d = idx - o * L_;
        sW3[o * 69 + d] = W3[idx];
        sW4[o * 69 + d] = W4[idx];
        sW5[o * 69 + d] = W5[idx];
    }
    for (int idx = tid; idx < L_; idx += 256) {
        sb3[idx] = b3[idx]; sb4[idx] = b4[idx]; sb5[idx] = b5[idx];
    }
    __syncthreads();

    const int lane = tid & 31, w = tid >> 5;
    const int row = blockIdx.x * 8 + w;
    const float* murow  = mu + (size_t)row * L_;
    const float* lvrow  = logvar + (size_t)row * L_;
    const float* epsrow = eps + (size_t)row * L_;
    float* zw  = zs + w * L_;
    float* h3w = h3s + w * L_;
    float* h4w = h4s + w * L_;

    float yp = 0.f;
    for (int o = lane; o < L_; o += 32) {
        float m_ = murow[o];
        zw[o] = m_ + epsrow[o] * expf(0.5f * lvrow[o]);
        yp += m_ * fcy_w[o];
    }
#pragma unroll
    for (int off = 16; off; off >>= 1) yp += __shfl_xor_sync(0xffffffffu, yp, off);
    if (lane == 0) y[row] = yp + fcy_b[0];
    __syncwarp();

    for (int o = lane; o < L_; o += 32) {
        float sacc = sb3[o];
        const float* wr = sW3 + o * 69;
#pragma unroll 4
        for (int d = 0; d < L_; d++) sacc += zw[d] * wr[d];
        h3w[o] = sacc;                  // branch 0: NO sigmoid
    }
    __syncwarp();
    for (int o = lane; o < L_; o += 32) {
        float sacc = sb4[o];
        const float* wr = sW4 + o * 69;
#pragma unroll 4
        for (int d = 0; d < L_; d++) sacc += h3w[d] * wr[d];
        h4w[o] = 1.0f / (1.0f + expf(-sacc));
    }
    __syncwarp();
    for (int o = lane; o < L_; o += 32) {
        float sacc = sb5[o];
        const float* wr = sW5 + o * 69;
#pragma unroll 4
        for (int d = 0; d < L_; d++) sacc += h4w[d] * wr[d];
        h51[(size_t)row * L_ + o] = sacc;
    }
}

// ============================ launch ============================
extern "C" void kernel_launch(void* const* d_in, const int* in_sizes, int n_in,
                              void* d_out, int out_size)
{
    const float* x      = (const float*)d_in[0];
    const float* eps    = (const float*)d_in[1];
    const float* fc11_w = (const float*)d_in[2];
    const float* fc11_b = (const float*)d_in[3];
    const float* fc12_w = (const float*)d_in[4];
    const float* fc12_b = (const float*)d_in[5];
    const float* fc21_w = (const float*)d_in[6];
    const float* fc21_b = (const float*)d_in[7];
    const float* fc22_w = (const float*)d_in[8];
    const float* fc22_b = (const float*)d_in[9];
    const float* W3     = (const float*)d_in[10];
    const float* b3     = (const float*)d_in[11];
    const float* W4     = (const float*)d_in[12];
    const float* b4     = (const float*)d_in[13];
    const float* W5     = (const float*)d_in[14];
    const float* b5     = (const float*)d_in[15];
    const float* fc6_w  = (const float*)d_in[16];
    const float* fc6_b  = (const float*)d_in[17];
    const float* fcy_w  = (const float*)d_in[18];
    const float* fcy_b  = (const float*)d_in[19];

    float* out   = (float*)d_out;
    float* recon = out;
    float* mu    = out + (size_t)B_ * D_;
    float* lv    = mu + (size_t)B_ * L_;
    float* y     = lv + (size_t)B_ * L_;

    __half* x16;  cudaGetSymbolAddress((void**)&x16, g_x16);
    __half* h16;  cudaGetSymbolAddress((void**)&h16, g_h16);
    __half* w1h;  cudaGetSymbolAddress((void**)&w1h, g_w1h);
    __half* w2h;  cudaGetSymbolAddress((void**)&w2h, g_w2h);
    __half* w6h;  cudaGetSymbolAddress((void**)&w6h, g_w6h);
    float*  h51;  cudaGetSymbolAddress((void**)&h51, g_h51);
    float*  b1;   cudaGetSymbolAddress((void**)&b1,  g_b1);

    // pre-pass: convert GEMM operands to fp16 (HBM-bound, ~40us total)
    const int CT = 256, CB = 1024;
    f32_to_f16_v4<<<CB, CT>>>((const float4*)x,      (uint2*)x16, (B_ * D_) / 4);
    f32_to_f16_v4<<<CB, CT>>>((const float4*)fc11_w, (uint2*)w1h,                     (E_ * D_) / 4);
    f32_to_f16_v4<<<CB, CT>>>((const float4*)fc12_w, (uint2*)(w1h + (size_t)E_ * D_), (E_ * D_) / 4);
    f32_to_f16_v4<<<CB, CT>>>((const float4*)fc21_w, (uint2*)w2h,                     (L_ * E_) / 4);
    f32_to_f16_v4<<<CB, CT>>>((const float4*)fc22_w, (uint2*)(w2h + (size_t)L_ * E_), (L_ * E_) / 4);
    f32_to_f16_v4<<<CB, CT>>>((const float4*)fc6_w,  (uint2*)w6h, (D_ * D_) / 4);
    cudaMemcpyAsync(b1,      fc11_b, E_ * sizeof(float), cudaMemcpyDeviceToDevice);
    cudaMemcpyAsync(b1 + E_, fc12_b, E_ * sizeof(float), cudaMemcpyDeviceToDevice);

    const size_t smemEnc  = (size_t)6 * STAGE_BYTES;                    // 61440
    const size_t smemRec  = (size_t)(128 * L_ * 4) + 6 * STAGE_BYTES;   // 96256
    const size_t smemHead = (size_t)4 * STAGE_BYTES;                    // 40960
    const size_t smemMid  = (size_t)(3 * L_ * 69 + 3 * L_ + 3 * 8 * L_) * 4;

    cudaFuncSetAttribute(gemm_f16<0>, cudaFuncAttributeMaxDynamicSharedMemorySize, (int)smemEnc);
    cudaFuncSetAttribute(gemm_f16<2>, cudaFuncAttributeMaxDynamicSharedMemorySize, (int)smemRec);
    cudaFuncSetAttribute(gemm_head,   cudaFuncAttributeMaxDynamicSharedMemorySize, (int)smemHead);
    cudaFuncSetAttribute(mid_kernel,  cudaFuncAttributeMaxDynamicSharedMemorySize, (int)smemMid);

    // 1) h16 = fp16(relu(x @ [fc11|fc12]^T + b))   [4096 x 2048]
    gemm_f16<0><<<dim3(2 * E_ / BN, B_ / BM), THREADS, smemEnc>>>(
        x16, D_, w1h, b1, nullptr, h16, 2 * E_, 2 * E_, D_, 2 * E_);

    // 2) mu / logvar heads  [4096 x 68], z-batched
    gemm_head<<<dim3(1, B_ / BM, 2), THREADS, smemHead>>>(
        h16, w2h, fc21_b, fc22_b, mu, B_ * L_);

    // 3) reparam + y + decoder branch 0 -> h51
    mid_kernel<<<B_ / 8, 256, smemMid>>>(
        mu, lv, eps, W3, b3, W4, b4, W5, b5, fcy_w, fcy_b, h51, y);

    // 4) recon = sigmoid(outer(h51) @ fc6_w^T + b)  [4096 x 4624]
    gemm_f16<2><<<dim3((D_ + BN - 1) / BN, B_ / BM), THREADS, smemRec>>>(
        nullptr, 0, w6h, fc6_b, h51, recon, D_, D_, D_, D_);
}

// round 8
// speedup vs baseline: 2.3435x; 1.4142x over previous
#include <cuda_runtime.h>
#include <cuda_fp16.h>
#include <cstdint>

// Problem dims
#define B_  4096
#define D_  4624
#define L_  68
#define E_  1024

// Symmetrized recon K: 68*69/2 = 2346 unique quadratic-form terms, padded to 74*32
#define KS_    2346
#define KS_PAD 2368

// fp16 mma.m16n8k16 + ldmatrix path (tcgen05 unavailable: harness targets compute_103)
#define BM 128
#define BN 128
#define BK 32              // k-elements per tile
#define KPADH 20           // smem row stride in u32 (16 data + 4 pad) — conflict-free
#define STAGEH_U32 (128 * KPADH)       // 2560 u32 = 10240 B per operand stage
#define STAGE_BYTES (STAGEH_U32 * 4)
#define THREADS 256

// ---- static scratch (no cudaMalloc allowed) ----
__device__ __half   g_x16[(size_t)B_ * D_];        // x, fp16
__device__ __half   g_h16[(size_t)B_ * 2 * E_];    // relu(x@fc11^T)|relu(x@fc12^T), fp16
__device__ __half   g_w1h[(size_t)2 * E_ * D_];    // fc11_w|fc12_w concat, fp16
__device__ __half   g_w2h[(size_t)2 * L_ * E_];    // fc21_w|fc22_w concat, fp16
__device__ __half   g_w6s[(size_t)D_ * KS_PAD];    // symmetrized fc6_w, fp16
__device__ uint16_t g_pairs[KS_PAD];               // pair p -> (i<<8)|j, i<=j
__device__ float    g_h51[(size_t)B_ * L_];        // decoder branch-0 output (f32)
__device__ float    g_b1 [2 * E_];                 // fc11_b|fc12_b concat (f32)

// ============================ helpers ============================
__device__ __forceinline__ void mma_f16(float* c, uint32_t a0, uint32_t a1,
                                        uint32_t a2, uint32_t a3,
                                        uint32_t b0, uint32_t b1) {
    asm volatile(
        "mma.sync.aligned.m16n8k16.row.col.f32.f16.f16.f32 "
        "{%0,%1,%2,%3}, {%4,%5,%6,%7}, {%8,%9}, {%0,%1,%2,%3};\n"
        : "+f"(c[0]), "+f"(c[1]), "+f"(c[2]), "+f"(c[3])
        : "r"(a0), "r"(a1), "r"(a2), "r"(a3), "r"(b0), "r"(b1));
}

__device__ __forceinline__ void ldmatrix_x4(uint32_t& d0, uint32_t& d1,
                                            uint32_t& d2, uint32_t& d3, uint32_t addr) {
    asm volatile("ldmatrix.sync.aligned.m8n8.x4.shared.b16 {%0,%1,%2,%3}, [%4];"
                 : "=r"(d0), "=r"(d1), "=r"(d2), "=r"(d3) : "r"(addr));
}

__device__ __forceinline__ void cp_async16(void* sptr, const void* gptr, int src_size) {
    uint32_t s = (uint32_t)__cvta_generic_to_shared(sptr);
    asm volatile("cp.async.cg.shared.global [%0], [%1], 16, %2;\n"
                 :: "r"(s), "l"(gptr), "r"(src_size));
}
__device__ __forceinline__ void cp_commit() { asm volatile("cp.async.commit_group;\n"); }
template <int N>
__device__ __forceinline__ void cp_wait() { asm volatile("cp.async.wait_group %0;\n" :: "n"(N)); }

__device__ __forceinline__ uint32_t pack_h2(float a, float b) {
    __half2 h = __floats2half2_rn(a, b);
    return *reinterpret_cast<uint32_t*>(&h);
}

// ============================ pre-pass kernels ============================
__global__ void f32_to_f16_v4(const float4* __restrict__ in, uint2* __restrict__ out, int n4) {
    int i = blockIdx.x * blockDim.x + threadIdx.x;
    int stride = gridDim.x * blockDim.x;
    for (; i < n4; i += stride) {
        float4 v = in[i];
        out[i] = make_uint2(pack_h2(v.x, v.y), pack_h2(v.z, v.w));
    }
}

// pair table: p -> (i,j), i<=j, upper-triangular row-major: p = i*68 - i(i-1)/2 + (j-i)
__global__ void build_pairs(uint16_t* __restrict__ pairs) {
    int p = blockIdx.x * blockDim.x + threadIdx.x;
    if (p >= KS_PAD) return;
    if (p >= KS_) { pairs[p] = 0; return; }
    int i = 0, base = 0;
    for (int q = 0; q < L_; q++) {
        int rowlen = L_ - q;
        if (p < base + rowlen) { i = q; break; }
        base += rowlen;
    }
    int j = i + (p - base);
    pairs[p] = (uint16_t)((i << 8) | j);
}

// fold fc6_w rows into symmetric-pair weights: Wsym[o,p] = G_ij + G_ji (i<j), G_ii (i==j)
__global__ void build_w6s(const float* __restrict__ w6,
                          const uint16_t* __restrict__ pairs,
                          __half* __restrict__ w6s) {
    __shared__ float row[D_];
    const int o = blockIdx.x;
    const float* src = w6 + (size_t)o * D_;
    for (int i = threadIdx.x; i < D_; i += 256) row[i] = src[i];
    __syncthreads();
    for (int p = threadIdx.x; p < KS_PAD; p += 256) {
        float v = 0.f;
        if (p < KS_) {
            uint16_t pr = pairs[p];
            int i = pr >> 8, j = pr & 255;
            v = row[i * L_ + j];
            if (i != j) v += row[j * L_ + i];
        }
        w6s[(size_t)o * KS_PAD + p] = __float2half_rn(v);
    }
}

// ============================ main GEMMs (fp16, ldmatrix, 3-stage) ============================
// MODE 0: h16 = fp16(relu(A16 @ W16^T + bias))     (encoder fc11|fc12 concat)
// MODE 2: C = sigmoid(sympairs(h51) @ W6s^T + bias) (recon; A = h_i*h_j pair products)
template <int MODE>
__global__ void __launch_bounds__(THREADS, 2)
gemm_f16(const __half* __restrict__ A, int lda,
         const __half* __restrict__ W, const float* __restrict__ bias,
         const float* __restrict__ h51, const uint16_t* __restrict__ gpairs,
         void* __restrict__ Cout, int ldc, int N, int K, int Nw)
{
    extern __shared__ unsigned char smem_raw[];
    uint32_t* sm = reinterpret_cast<uint32_t*>(smem_raw);

    // MODE 2 layout: h51s f32 [128*68] | pairs u16 [KS_PAD] | As(3) | Bs(3)
    float*     h51s  = reinterpret_cast<float*>(sm);
    uint16_t*  pairS = reinterpret_cast<uint16_t*>(sm + 128 * L_);
    uint32_t*  As    = (MODE == 2) ? (sm + 128 * L_ + KS_PAD / 2) : sm;
    uint32_t*  Bs    = As + 3 * STAGEH_U32;

    const int tid  = threadIdx.x;
    const int lane = tid & 31;
    const int warp = tid >> 5;
    const int wm   = warp & 3;          // 4 warps along M (32 rows each)
    const int wn   = warp >> 2;         // 2 warps along N (64 cols each)
    const int grp  = lane >> 2;
    const int tig  = lane & 3;
    const int m0   = blockIdx.y * BM;
    const int n0   = blockIdx.x * BN;
    const int kt   = (K + BK - 1) / BK;

    if (MODE == 2) {
        for (int idx = tid; idx < BM * L_; idx += THREADS)
            h51s[idx] = h51[(size_t)m0 * L_ + idx];
        for (int idx = tid; idx < KS_PAD; idx += THREADS)
            pairS[idx] = gpairs[idx];
        __syncthreads();
    }

    const uint32_t As_b = (uint32_t)__cvta_generic_to_shared(As);
    const uint32_t Bs_b = (uint32_t)__cvta_generic_to_shared(Bs);

    // per-lane ldmatrix source coordinates
    const int aRow  = wm * 32 + ((lane >> 3) & 1) * 8 + (lane & 7);  // + mt*16
    const int aColB = (lane >> 4) * 16;
    const int bRow  = wn * 64 + (lane >> 4) * 8 + (lane & 7);        // + nt16*16
    const int bColB = ((lane >> 3) & 1) * 16;

    auto prefetch = [&](int t) {
        const int s  = t % 3;
        const int k0 = t * BK;
        uint32_t* Ab = As + s * STAGEH_U32;
        uint32_t* Bb = Bs + s * STAGEH_U32;
        if (MODE == 0) {
#pragma unroll
            for (int i = 0; i < 2; i++) {
                int q = tid + i * 256;
                int r = q >> 2, ch = q & 3;
                int k = k0 + ch * 8;
                cp_async16(Ab + r * KPADH + ch * 4,
                           A + (size_t)(m0 + r) * lda + k, (k < K) ? 16 : 0);
            }
        } else {
            // A: symmetric pair products h_i*h_j, fp16, STS.128
#pragma unroll
            for (int i = 0; i < 2; i++) {
                int q = tid + i * 256;
                int r = q >> 2, ch = q & 3;
                int kb = k0 + ch * 8;
                const float* hr = h51s + r * L_;
                uint32_t v[4];
#pragma unroll
                for (int p = 0; p < 4; p++) {
                    uint16_t p0 = pairS[kb + 2 * p];
                    uint16_t p1 = pairS[kb + 2 * p + 1];
                    float f0 = hr[p0 >> 8] * hr[p0 & 255];
                    float f1 = hr[p1 >> 8] * hr[p1 & 255];
                    v[p] = pack_h2(f0, f1);
                }
                uint32_t daddr = (uint32_t)__cvta_generic_to_shared(Ab + r * KPADH + ch * 4);
                asm volatile("st.shared.v4.b32 [%0], {%1,%2,%3,%4};"
                             :: "r"(daddr), "r"(v[0]), "r"(v[1]), "r"(v[2]), "r"(v[3])
                             : "memory");
            }
        }
        // B: weights [Nw, K] row-major (NT gemm), fp16
#pragma unroll
        for (int i = 0; i < 2; i++) {
            int q = tid + i * 256;
            int r = q >> 2, ch = q & 3;
            int k = k0 + ch * 8;
            int row = n0 + r;
            const __half* src = W + (size_t)(row < Nw ? row : 0) * K + k;
            cp_async16(Bb + r * KPADH + ch * 4, src, (row < Nw && k < K) ? 16 : 0);
        }
        cp_commit();
    };

    float acc[2][8][4] = {};

    auto compute = [&](int buf) {
        const uint32_t abase = As_b + buf * STAGE_BYTES;
        const uint32_t bbase = Bs_b + buf * STAGE_BYTES;
#pragma unroll
        for (int kk = 0; kk < 2; kk++) {              // two k16 steps per k32 tile
            const int kb = kk * 32;
            uint32_t a[2][4];
#pragma unroll
            for (int mt = 0; mt < 2; mt++)
                ldmatrix_x4(a[mt][0], a[mt][1], a[mt][2], a[mt][3],
                            abase + (uint32_t)(aRow + mt * 16) * (KPADH * 4) + kb + aColB);
#pragma unroll
            for (int nt16 = 0; nt16 < 4; nt16++) {
                uint32_t b0, b1, b2, b3;
                ldmatrix_x4(b0, b1, b2, b3,
                            bbase + (uint32_t)(bRow + nt16 * 16) * (KPADH * 4) + kb + bColB);
#pragma unroll
                for (int mt = 0; mt < 2; mt++) {
                    mma_f16(acc[mt][nt16 * 2 + 0], a[mt][0], a[mt][1], a[mt][2], a[mt][3], b0, b1);
                    mma_f16(acc[mt][nt16 * 2 + 1], a[mt][0], a[mt][1], a[mt][2], a[mt][3], b2, b3);
                }
            }
        }
    };

    // 3-stage pipeline, one __syncthreads per iteration
    prefetch(0);
    prefetch(1);
    for (int t = 0; t < kt; t++) {
        if (t < kt - 1) cp_wait<1>(); else cp_wait<0>();
        __syncthreads();
        if (t + 2 < kt) prefetch(t + 2);
        compute(t % 3);
    }

    // Epilogue
#pragma unroll
    for (int mt = 0; mt < 2; mt++) {
        int row = m0 + wm * 32 + mt * 16 + grp;
#pragma unroll
        for (int nt = 0; nt < 8; nt++) {
            int ncl = wn * 64 + nt * 8 + tig * 2;
#pragma unroll
            for (int half = 0; half < 2; half++) {
                int r   = row + half * 8;
                int col = n0 + ncl;
                float v0 = acc[mt][nt][half * 2 + 0] + bias[col];
                float v1 = acc[mt][nt][half * 2 + 1] + ((col + 1 < N) ? bias[col + 1] : 0.f);
                if (MODE == 0) {
                    v0 = v0 > 0.f ? v0 : 0.f;
                    v1 = v1 > 0.f ? v1 : 0.f;
                    *reinterpret_cast<uint32_t*>(
                        (__half*)Cout + (size_t)r * ldc + col) = pack_h2(v0, v1);
                } else {
                    float* C = (float*)Cout;
                    if (col < N)     C[(size_t)r * ldc + col]     = 1.0f / (1.0f + __expf(-v0));
                    if (col + 1 < N) C[(size_t)r * ldc + col + 1] = 1.0f / (1.0f + __expf(-v1));
                }
            }
        }
    }
}

// ============================ head GEMM (mu / logvar), fp16 ============================
__global__ void __launch_bounds__(THREADS, 2)
gemm_head(const __half* __restrict__ Abase, const __half* __restrict__ Wbase,
          const float* __restrict__ bias0, const float* __restrict__ bias1,
          float* __restrict__ Cbase, int batchStrideC)
{
    extern __shared__ unsigned char smem_raw[];
    uint32_t* As = reinterpret_cast<uint32_t*>(smem_raw);
    uint32_t* Bs = As + 2 * STAGEH_U32;

    const int tid = threadIdx.x;
    const int m0  = blockIdx.y * BM;
    const int N = L_, K = E_;

    const int z = blockIdx.z;
    const __half* A    = Abase + (size_t)z * E_;
    const __half* W    = Wbase + (size_t)z * L_ * E_;
    const float* bias  = z ? bias1 : bias0;
    float* C           = Cbase + (size_t)z * batchStrideC;

    const int lane = tid & 31;
    const int warp = tid >> 5;
    const int wm = warp & 3;
    const int wn = warp >> 2;
    const int grp = lane >> 2;
    const int tig = lane & 3;

    const uint32_t As_b = (uint32_t)__cvta_generic_to_shared(As);
    const uint32_t Bs_b = (uint32_t)__cvta_generic_to_shared(Bs);
    const int aRow  = wm * 32 + ((lane >> 3) & 1) * 8 + (lane & 7);
    const int aColB = (lane >> 4) * 16;
    const int bRow  = wn * 64 + (lane >> 4) * 8 + (lane & 7);
    const int bColB = ((lane >> 3) & 1) * 16;

    auto prefetch = [&](int t) {
        const int buf = t & 1;
        const int k0  = t * BK;
        uint32_t* Ab = As + buf * STAGEH_U32;
        uint32_t* Bb = Bs + buf * STAGEH_U32;
#pragma unroll
        for (int i = 0; i < 2; i++) {
            int q = tid + i * 256;
            int r = q >> 2, ch = q & 3;
            int k = k0 + ch * 8;
            cp_async16(Ab + r * KPADH + ch * 4,
                       A + (size_t)(m0 + r) * (2 * E_) + k, 16);
            const __half* src = W + (size_t)(r < N ? r : 0) * K + k;
            cp_async16(Bb + r * KPADH + ch * 4, src, (r < N) ? 16 : 0);
        }
        cp_commit();
    };

    float acc[2][8][4] = {};

    auto compute = [&](int buf) {
        const uint32_t abase = As_b + buf * STAGE_BYTES;
        const uint32_t bbase = Bs_b + buf * STAGE_BYTES;
#pragma unroll
        for (int kk = 0; kk < 2; kk++) {
            const int kb = kk * 32;
            uint32_t a[2][4];
#pragma unroll
            for (int mt = 0; mt < 2; mt++)
                ldmatrix_x4(a[mt][0], a[mt][1], a[mt][2], a[mt][3],
                            abase + (uint32_t)(aRow + mt * 16) * (KPADH * 4) + kb + aColB);
#pragma unroll
            for (int nt16 = 0; nt16 < 4; nt16++) {
                uint32_t b0, b1, b2, b3;
                ldmatrix_x4(b0, b1, b2, b3,
                            bbase + (uint32_t)(bRow + nt16 * 16) * (KPADH * 4) + kb + bColB);
#pragma unroll
                for (int mt = 0; mt < 2; mt++) {
                    mma_f16(acc[mt][nt16 * 2 + 0], a[mt][0], a[mt][1], a[mt][2], a[mt][3], b0, b1);
                    mma_f16(acc[mt][nt16 * 2 + 1], a[mt][0], a[mt][1], a[mt][2], a[mt][3], b2, b3);
                }
            }
        }
    };

    const int kt = K / BK;
    prefetch(0);
    for (int t = 0; t < kt; t++) {
        if (t + 1 < kt) { prefetch(t + 1); cp_wait<1>(); }
        else            { cp_wait<0>(); }
        __syncthreads();
        compute(t & 1);
        __syncthreads();
    }

#pragma unroll
    for (int mt = 0; mt < 2; mt++) {
        int row = m0 + wm * 32 + mt * 16 + grp;
#pragma unroll
        for (int nt = 0; nt < 8; nt++) {
            int ncl = wn * 64 + nt * 8 + tig * 2;
#pragma unroll
            for (int e = 0; e < 4; e++) {
                int r   = row + ((e >= 2) ? 8 : 0);
                int col = ncl + (e & 1);
                if (col < N)
                    C[(size_t)r * N + col] = acc[mt][nt][e] + bias[col];
            }
        }
    }
}

// ============================ mid kernel ============================
// z = mu + eps*exp(0.5*logvar); y = mu@fcy^T+b; decoder branch 0 only (others dead)
__global__ void __launch_bounds__(256, 1)
mid_kernel(const float* __restrict__ mu, const float* __restrict__ logvar,
           const float* __restrict__ eps,
           const float* __restrict__ W3, const float* __restrict__ b3,
           const float* __restrict__ W4, const float* __restrict__ b4,
           const float* __restrict__ W5, const float* __restrict__ b5,
           const float* __restrict__ fcy_w, const float* __restrict__ fcy_b,
           float* __restrict__ h51, float* __restrict__ y)
{
    extern __shared__ unsigned char smem_raw[];
    float* s   = reinterpret_cast<float*>(smem_raw);
    float* sW3 = s;
    float* sW4 = sW3 + L_ * 69;
    float* sW5 = sW4 + L_ * 69;
    float* sb3 = sW5 + L_ * 69;
    float* sb4 = sb3 + L_;
    float* sb5 = sb4 + L_;
    float* zs  = sb5 + L_;
    float* h3s = zs + 8 * L_;
    float* h4s = h3s + 8 * L_;

    const int tid = threadIdx.x;
    for (int idx = tid; idx < L_ * L_; idx += 256) {
        int o = idx / L_, d = idx - o * L_;
        sW3[o * 69 + d] = W3[idx];
        sW4[o * 69 + d] = W4[idx];
        sW5[o * 69 + d] = W5[idx];
    }
    for (int idx = tid; idx < L_; idx += 256) {
        sb3[idx] = b3[idx]; sb4[idx] = b4[idx]; sb5[idx] = b5[idx];
    }
    __syncthreads();

    const int lane = tid & 31, w = tid >> 5;
    const int row = blockIdx.x * 8 + w;
    const float* murow  = mu + (size_t)row * L_;
    const float* lvrow  = logvar + (size_t)row * L_;
    const float* epsrow = eps + (size_t)row * L_;
    float* zw  = zs + w * L_;
    float* h3w = h3s + w * L_;
    float* h4w = h4s + w * L_;

    float yp = 0.f;
    for (int o = lane; o < L_; o += 32) {
        float m_ = murow[o];
        zw[o] = m_ + epsrow[o] * expf(0.5f * lvrow[o]);
        yp += m_ * fcy_w[o];
    }
#pragma unroll
    for (int off = 16; off; off >>= 1) yp += __shfl_xor_sync(0xffffffffu, yp, off);
    if (lane == 0) y[row] = yp + fcy_b[0];
    __syncwarp();

    for (int o = lane; o < L_; o += 32) {
        float sacc = sb3[o];
        const float* wr = sW3 + o * 69;
#pragma unroll 4
        for (int d = 0; d < L_; d++) sacc += zw[d] * wr[d];
        h3w[o] = sacc;                  // branch 0: NO sigmoid
    }
    __syncwarp();
    for (int o = lane; o < L_; o += 32) {
        float sacc = sb4[o];
        const float* wr = sW4 + o * 69;
#pragma unroll 4
        for (int d = 0; d < L_; d++) sacc += h3w[d] * wr[d];
        h4w[o] = 1.0f / (1.0f + expf(-sacc));
    }
    __syncwarp();
    for (int o = lane; o < L_; o += 32) {
        float sacc = sb5[o];
        const float* wr = sW5 + o * 69;
#pragma unroll 4
        for (int d = 0; d < L_; d++) sacc += h4w[d] * wr[d];
        h51[(size_t)row * L_ + o] = sacc;
    }
}

// ============================ launch ============================
extern "C" void kernel_launch(void* const* d_in, const int* in_sizes, int n_in,
                              void* d_out, int out_size)
{
    const float* x      = (const float*)d_in[0];
    const float* eps    = (const float*)d_in[1];
    const float* fc11_w = (const float*)d_in[2];
    const float* fc11_b = (const float*)d_in[3];
    const float* fc12_w = (const float*)d_in[4];
    const float* fc12_b = (const float*)d_in[5];
    const float* fc21_w = (const float*)d_in[6];
    const float* fc21_b = (const float*)d_in[7];
    const float* fc22_w = (const float*)d_in[8];
    const float* fc22_b = (const float*)d_in[9];
    const float* W3     = (const float*)d_in[10];
    const float* b3     = (const float*)d_in[11];
    const float* W4     = (const float*)d_in[12];
    const float* b4     = (const float*)d_in[13];
    const float* W5     = (const float*)d_in[14];
    const float* b5     = (const float*)d_in[15];
    const float* fc6_w  = (const float*)d_in[16];
    const float* fc6_b  = (const float*)d_in[17];
    const float* fcy_w  = (const float*)d_in[18];
    const float* fcy_b  = (const float*)d_in[19];

    float* out   = (float*)d_out;
    float* recon = out;
    float* mu    = out + (size_t)B_ * D_;
    float* lv    = mu + (size_t)B_ * L_;
    float* y     = lv + (size_t)B_ * L_;

    __half*   x16;  cudaGetSymbolAddress((void**)&x16, g_x16);
    __half*   h16;  cudaGetSymbolAddress((void**)&h16, g_h16);
    __half*   w1h;  cudaGetSymbolAddress((void**)&w1h, g_w1h);
    __half*   w2h;  cudaGetSymbolAddress((void**)&w2h, g_w2h);
    __half*   w6s;  cudaGetSymbolAddress((void**)&w6s, g_w6s);
    uint16_t* prs;  cudaGetSymbolAddress((void**)&prs, g_pairs);
    float*    h51;  cudaGetSymbolAddress((void**)&h51, g_h51);
    float*    b1;   cudaGetSymbolAddress((void**)&b1,  g_b1);

    // pre-pass: fp16 conversions + symmetric fold of fc6_w
    const int CT = 256, CB = 1024;
    f32_to_f16_v4<<<CB, CT>>>((const float4*)x,      (uint2*)x16, (B_ * D_) / 4);
    f32_to_f16_v4<<<CB, CT>>>((const float4*)fc11_w, (uint2*)w1h,                     (E_ * D_) / 4);
    f32_to_f16_v4<<<CB, CT>>>((const float4*)fc12_w, (uint2*)(w1h + (size_t)E_ * D_), (E_ * D_) / 4);
    f32_to_f16_v4<<<CB, CT>>>((const float4*)fc21_w, (uint2*)w2h,                     (L_ * E_) / 4);
    f32_to_f16_v4<<<CB, CT>>>((const float4*)fc22_w, (uint2*)(w2h + (size_t)L_ * E_), (L_ * E_) / 4);
    build_pairs<<<(KS_PAD + 255) / 256, 256>>>(prs);
    build_w6s<<<D_, 256>>>(fc6_w, prs, w6s);
    cudaMemcpyAsync(b1,      fc11_b, E_ * sizeof(float), cudaMemcpyDeviceToDevice);
    cudaMemcpyAsync(b1 + E_, fc12_b, E_ * sizeof(float), cudaMemcpyDeviceToDevice);

    const size_t smemEnc  = (size_t)6 * STAGE_BYTES;                               // 61440
    const size_t smemRec  = (size_t)(128 * L_ * 4) + KS_PAD * 2 + 6 * STAGE_BYTES; // 100992
    const size_t smemHead = (size_t)4 * STAGE_BYTES;                               // 40960
    const size_t smemMid  = (size_t)(3 * L_ * 69 + 3 * L_ + 3 * 8 * L_) * 4;

    cudaFuncSetAttribute(gemm_f16<0>, cudaFuncAttributeMaxDynamicSharedMemorySize, (int)smemEnc);
    cudaFuncSetAttribute(gemm_f16<2>, cudaFuncAttributeMaxDynamicSharedMemorySize, (int)smemRec);
    cudaFuncSetAttribute(gemm_head,   cudaFuncAttributeMaxDynamicSharedMemorySize, (int)smemHead);
    cudaFuncSetAttribute(mid_kernel,  cudaFuncAttributeMaxDynamicSharedMemorySize, (int)smemMid);

    // 1) h16 = fp16(relu(x @ [fc11|fc12]^T + b))   [4096 x 2048]
    gemm_f16<0><<<dim3(2 * E_ / BN, B_ / BM), THREADS, smemEnc>>>(
        x16, D_, w1h, b1, nullptr, nullptr, h16, 2 * E_, 2 * E_, D_, 2 * E_);

    // 2) mu / logvar heads  [4096 x 68], z-batched
    gemm_head<<<dim3(1, B_ / BM, 2), THREADS, smemHead>>>(
        h16, w2h, fc21_b, fc22_b, mu, B_ * L_);

    // 3) reparam + y + decoder branch 0 -> h51
    mid_kernel<<<B_ / 8, 256, smemMid>>>(
        mu, lv, eps, W3, b3, W4, b4, W5, b5, fcy_w, fcy_b, h51, y);

    // 4) recon = sigmoid(sympairs(h51) @ w6s^T + b)  [4096 x 4624], K=2368
    gemm_f16<2><<<dim3((D_ + BN - 1) / BN, B_ / BM), THREADS, smemRec>>>(
        nullptr, 0, w6s, fc6_b, h51, prs, recon, D_, D_, KS_PAD, D_);
}

// round 11
// speedup vs baseline: 2.4864x; 1.0610x over previous
#include <cuda_runtime.h>
#include <cuda_fp16.h>
#include <cstdint>

// Problem dims
#define B_  4096
#define D_  4624
#define L_  68
#define E_  1024

// Symmetrized recon K: 68*69/2 = 2346 unique quadratic-form terms, padded to 37*64
#define KS_    2346
#define KS_PAD 2368

// fp16 mma.m16n8k16 + ldmatrix path (tcgen05 unavailable: harness targets compute_103)
#define BM 128
#define BN 128
#define THREADS 256

// BK=64 tiles for the two large GEMMs
#define BK2 64
#define KP2 36                       // u32 per smem row (32 data + 4 pad)
#define STG2_U32 (128 * KP2)         // 4608 u32
#define STG2_B   (STG2_U32 * 4)      // 18432 B per operand stage

// BK=32 constants (head GEMM only)
#define KPADH 20
#define STAGEH_U32 (128 * KPADH)
#define STAGE_BYTES (STAGEH_U32 * 4)

// ---- static scratch (no cudaMalloc allowed) ----
__device__ __half   g_x16[(size_t)B_ * D_];
__device__ __half   g_h16[(size_t)B_ * 2 * E_];
__device__ __half   g_w1h[(size_t)2 * E_ * D_];
__device__ __half   g_w2h[(size_t)2 * L_ * E_];
__device__ __half   g_w6s[(size_t)D_ * KS_PAD];
__device__ uint16_t g_pairs[KS_PAD];
__device__ float    g_h51[(size_t)B_ * L_];
__device__ float    g_b1 [2 * E_];

// ============================ helpers ============================
__device__ __forceinline__ void mma_f16(float* c, uint32_t a0, uint32_t a1,
                                        uint32_t a2, uint32_t a3,
                                        uint32_t b0, uint32_t b1) {
    asm volatile(
        "mma.sync.aligned.m16n8k16.row.col.f32.f16.f16.f32 "
        "{%0,%1,%2,%3}, {%4,%5,%6,%7}, {%8,%9}, {%0,%1,%2,%3};\n"
        : "+f"(c[0]), "+f"(c[1]), "+f"(c[2]), "+f"(c[3])
        : "r"(a0), "r"(a1), "r"(a2), "r"(a3), "r"(b0), "r"(b1));
}

__device__ __forceinline__ void ldmatrix_x4(uint32_t& d0, uint32_t& d1,
                                            uint32_t& d2, uint32_t& d3, uint32_t addr) {
    asm volatile("ldmatrix.sync.aligned.m8n8.x4.shared.b16 {%0,%1,%2,%3}, [%4];"
                 : "=r"(d0), "=r"(d1), "=r"(d2), "=r"(d3) : "r"(addr));
}

__device__ __forceinline__ void cp_async16(void* sptr, const void* gptr, int src_size) {
    uint32_t s = (uint32_t)__cvta_generic_to_shared(sptr);
    asm volatile("cp.async.cg.shared.global [%0], [%1], 16, %2;\n"
                 :: "r"(s), "l"(gptr), "r"(src_size));
}
__device__ __forceinline__ void cp_commit() { asm volatile("cp.async.commit_group;\n"); }
template <int N>
__device__ __forceinline__ void cp_wait() { asm volatile("cp.async.wait_group %0;\n" :: "n"(N)); }

__device__ __forceinline__ uint32_t pack_h2(float a, float b) {
    __half2 h = __floats2half2_rn(a, b);
    return *reinterpret_cast<uint32_t*>(&h);
}
__device__ __forceinline__ uint2 cvt4(float4 v) {
    return make_uint2(pack_h2(v.x, v.y), pack_h2(v.z, v.w));
}

// ============================ fused pre-pass ============================
__global__ void prep_all(const float4* __restrict__ x,
                         const float4* __restrict__ w11, const float4* __restrict__ w12,
                         const float4* __restrict__ w21, const float4* __restrict__ w22,
                         const float4* __restrict__ b11, const float4* __restrict__ b12,
                         uint2* __restrict__ x16, uint2* __restrict__ w1h,
                         uint2* __restrict__ w2h, float4* __restrict__ b1)
{
    const int NX  = (B_ * D_) / 4;
    const int NW1 = (E_ * D_) / 4;
    const int NW2 = (L_ * E_) / 4;
    const int NB  = (2 * E_) / 4;
    const int T = NX + 2 * NW1 + 2 * NW2 + NB;
    for (int i = blockIdx.x * blockDim.x + threadIdx.x; i < T;
         i += gridDim.x * blockDim.x) {
        int j = i;
        if (j < NX)  { x16[j] = cvt4(x[j]); continue; }
        j -= NX;
        if (j < NW1) { w1h[j] = cvt4(w11[j]); continue; }
        j -= NW1;
        if (j < NW1) { w1h[NW1 + j] = cvt4(w12[j]); continue; }
        j -= NW1;
        if (j < NW2) { w2h[j] = cvt4(w21[j]); continue; }
        j -= NW2;
        if (j < NW2) { w2h[NW2 + j] = cvt4(w22[j]); continue; }
        j -= NW2;
        if (j < NB / 2) b1[j] = b11[j];
        else            b1[j] = b12[j - NB / 2];
    }
}

// pair table: p -> (i,j), i<=j, upper-triangular row-major
__global__ void build_pairs(uint16_t* __restrict__ pairs) {
    int p = blockIdx.x * blockDim.x + threadIdx.x;
    if (p >= KS_PAD) return;
    if (p >= KS_) { pairs[p] = 0; return; }
    int i = 0, base = 0;
    for (int q = 0; q < L_; q++) {
        int rowlen = L_ - q;
        if (p < base + rowlen) { i = q; break; }
        base += rowlen;
    }
    int j = i + (p - base);
    pairs[p] = (uint16_t)((i << 8) | j);
}

// fold fc6_w rows into symmetric-pair weights
__global__ void build_w6s(const float* __restrict__ w6,
                          const uint16_t* __restrict__ pairs,
                          __half* __restrict__ w6s) {
    __shared__ float row[D_];
    const int o = blockIdx.x;
    const float* src = w6 + (size_t)o * D_;
    for (int i = threadIdx.x; i < D_; i += 256) row[i] = src[i];
    __syncthreads();
    for (int p = threadIdx.x; p < KS_PAD; p += 256) {
        float v = 0.f;
        if (p < KS_) {
            uint16_t pr = pairs[p];
            int i = pr >> 8, j = pr & 255;
            v = row[i * L_ + j];
            if (i != j) v += row[j * L_ + i];
        }
        w6s[(size_t)o * KS_PAD + p] = __float2half_rn(v);
    }
}

// ============================ encoder GEMM (BK=64, 3+3 stages) ============================
// h16 = fp16(relu(x16 @ [fc11|fc12]^T + b1)) ; M=4096, N=2048, K=4624
__global__ void __launch_bounds__(THREADS, 2)
gemm_enc(const __half* __restrict__ A, const __half* __restrict__ W,
         const float* __restrict__ bias, __half* __restrict__ C)
{
    extern __shared__ unsigned char smem_raw[];
    uint32_t* sm = reinterpret_cast<uint32_t*>(smem_raw);
    uint32_t* As = sm;                      // 3 stages
    uint32_t* Bs = sm + 3 * STG2_U32;       // 3 stages

    const int K = D_, lda = D_, ldc = 2 * E_;
    const int tid  = threadIdx.x;
    const int lane = tid & 31;
    const int warp = tid >> 5;
    const int wm = warp & 3, wn = warp >> 2;
    const int grp = lane >> 2, tig = lane & 3;
    const int m0 = blockIdx.y * BM;
    const int n0 = blockIdx.x * BN;
    const int kt = (K + BK2 - 1) / BK2;     // 73

    const uint32_t As_b = (uint32_t)__cvta_generic_to_shared(As);
    const uint32_t Bs_b = (uint32_t)__cvta_generic_to_shared(Bs);
    const int aRow  = wm * 32 + ((lane >> 3) & 1) * 8 + (lane & 7);
    const int aColB = (lane >> 4) * 16;
    const int bRow  = wn * 64 + (lane >> 4) * 8 + (lane & 7);
    const int bColB = ((lane >> 3) & 1) * 16;

    auto prefetch = [&](int t) {
        const int s  = t % 3;
        const int k0 = t * BK2;
        uint32_t* Ab = As + s * STG2_U32;
        uint32_t* Bb = Bs + s * STG2_U32;
#pragma unroll
        for (int i = 0; i < 4; i++) {
            int q = tid + i * 256;
            int r = q >> 3, ch = q & 7;
            int k = k0 + ch * 8;
            int sz = (k < K) ? 16 : 0;
            cp_async16(Ab + r * KP2 + ch * 4, A + (size_t)(m0 + r) * lda + k, sz);
            cp_async16(Bb + r * KP2 + ch * 4, W + (size_t)(n0 + r) * K + k, sz);
        }
        cp_commit();
    };

    float acc[2][8][4] = {};

    auto compute = [&](int buf) {
        const uint32_t abase = As_b + buf * STG2_B;
        const uint32_t bbase = Bs_b + buf * STG2_B;
#pragma unroll
        for (int kk = 0; kk < 4; kk++) {
            const int kb = kk * 32;
            uint32_t a[2][4];
#pragma unroll
            for (int mt = 0; mt < 2; mt++)
                ldmatrix_x4(a[mt][0], a[mt][1], a[mt][2], a[mt][3],
                            abase + (uint32_t)(aRow + mt * 16) * (KP2 * 4) + kb + aColB);
#pragma unroll
            for (int nt16 = 0; nt16 < 4; nt16++) {
                uint32_t b0, b1, b2, b3;
                ldmatrix_x4(b0, b1, b2, b3,
                            bbase + (uint32_t)(bRow + nt16 * 16) * (KP2 * 4) + kb + bColB);
#pragma unroll
                for (int mt = 0; mt < 2; mt++) {
                    mma_f16(acc[mt][nt16 * 2 + 0], a[mt][0], a[mt][1], a[mt][2], a[mt][3], b0, b1);
                    mma_f16(acc[mt][nt16 * 2 + 1], a[mt][0], a[mt][1], a[mt][2], a[mt][3], b2, b3);
                }
            }
        }
    };

    // 3-stage pipeline: fills issued AFTER the barrier; writer stage t+2 is
    // disjoint from reader stages t (this iter) and t-1 (retired by barrier).
    prefetch(0);
    prefetch(1);
    for (int t = 0; t < kt; t++) {
        if (t < kt - 1) cp_wait<1>(); else cp_wait<0>();
        __syncthreads();
        if (t + 2 < kt) prefetch(t + 2);
        compute(t % 3);
    }

    // Epilogue: bias + relu -> fp16 (N=2048, no guards needed)
#pragma unroll
    for (int mt = 0; mt < 2; mt++) {
        int row = m0 + wm * 32 + mt * 16 + grp;
#pragma unroll
        for (int nt = 0; nt < 8; nt++) {
            int col = n0 + wn * 64 + nt * 8 + tig * 2;
#pragma unroll
            for (int half = 0; half < 2; half++) {
                int r = row + half * 8;
                float v0 = acc[mt][nt][half * 2 + 0] + bias[col];
                float v1 = acc[mt][nt][half * 2 + 1] + bias[col + 1];
                v0 = v0 > 0.f ? v0 : 0.f;
                v1 = v1 > 0.f ? v1 : 0.f;
                *reinterpret_cast<uint32_t*>(C + (size_t)r * ldc + col) = pack_h2(v0, v1);
            }
        }
    }
}

// ============================ recon GEMM (BK=64, 2+2 stages, synth A) ============================
// recon = sigmoid(sympairs(h51) @ w6s^T + fc6_b) ; M=4096, N=4624, K=2368
// Safe double-buffer shape: all stage fills issued AFTER the iteration barrier
// (the buffer they overwrite was read by compute(t-1), retired by that barrier).
// BUGFIX vs R10: compute(t & 1), not compute(t) — buf indexes 2 stages only.
__global__ void __launch_bounds__(THREADS, 2)
gemm_rec(const __half* __restrict__ W, const float* __restrict__ bias,
         const float* __restrict__ h51, const uint16_t* __restrict__ gpairs,
         float* __restrict__ C)
{
    extern __shared__ unsigned char smem_raw[];
    uint32_t* sm = reinterpret_cast<uint32_t*>(smem_raw);
    float*    h51s  = reinterpret_cast<float*>(sm);
    uint16_t* pairS = reinterpret_cast<uint16_t*>(sm + 128 * L_);
    uint32_t* As    = sm + 128 * L_ + KS_PAD / 2;   // 2 stages
    uint32_t* Bs    = As + 2 * STG2_U32;            // 2 stages

    const int K = KS_PAD, N = D_, Nw = D_, ldc = D_;
    const int tid  = threadIdx.x;
    const int lane = tid & 31;
    const int warp = tid >> 5;
    const int wm = warp & 3, wn = warp >> 2;
    const int grp = lane >> 2, tig = lane & 3;
    const int m0 = blockIdx.y * BM;
    const int n0 = blockIdx.x * BN;
    const int kt = K / BK2;                 // 37

    for (int idx = tid; idx < BM * L_; idx += THREADS)
        h51s[idx] = h51[(size_t)m0 * L_ + idx];
    for (int idx = tid; idx < KS_PAD; idx += THREADS)
        pairS[idx] = gpairs[idx];
    __syncthreads();

    const uint32_t As_b = (uint32_t)__cvta_generic_to_shared(As);
    const uint32_t Bs_b = (uint32_t)__cvta_generic_to_shared(Bs);
    const int aRow  = wm * 32 + ((lane >> 3) & 1) * 8 + (lane & 7);
    const int aColB = (lane >> 4) * 16;
    const int bRow  = wn * 64 + (lane >> 4) * 8 + (lane & 7);
    const int bColB = ((lane >> 3) & 1) * 16;

    auto synthA = [&](int t) {
        uint32_t* Ab = As + (t & 1) * STG2_U32;
        const int k0 = t * BK2;
#pragma unroll
        for (int i = 0; i < 4; i++) {
            int q = tid + i * 256;
            int r = q >> 3, ch = q & 7;
            int kb = k0 + ch * 8;
            const float* hr = h51s + r * L_;
            uint32_t v[4];
#pragma unroll
            for (int p = 0; p < 4; p++) {
                uint16_t p0 = pairS[kb + 2 * p];
                uint16_t p1 = pairS[kb + 2 * p + 1];
                float f0 = hr[p0 >> 8] * hr[p0 & 255];
                float f1 = hr[p1 >> 8] * hr[p1 & 255];
                v[p] = pack_h2(f0, f1);
            }
            uint32_t daddr = (uint32_t)__cvta_generic_to_shared(Ab + r * KP2 + ch * 4);
            asm volatile("st.shared.v4.b32 [%0], {%1,%2,%3,%4};"
                         :: "r"(daddr), "r"(v[0]), "r"(v[1]), "r"(v[2]), "r"(v[3])
                         : "memory");
        }
    };

    auto cpB = [&](int t) {
        uint32_t* Bb = Bs + (t & 1) * STG2_U32;
        const int k0 = t * BK2;
#pragma unroll
        for (int i = 0; i < 4; i++) {
            int q = tid + i * 256;
            int r = q >> 3, ch = q & 7;
            int k = k0 + ch * 8;
            int row = n0 + r;
            const __half* src = W + (size_t)(row < Nw ? row : 0) * K + k;
            cp_async16(Bb + r * KP2 + ch * 4, src, (row < Nw) ? 16 : 0);
        }
        cp_commit();
    };

    float acc[2][8][4] = {};

    auto compute = [&](int buf) {
        const uint32_t abase = As_b + buf * STG2_B;
        const uint32_t bbase = Bs_b + buf * STG2_B;
#pragma unroll
        for (int kk = 0; kk < 4; kk++) {
            const int kb = kk * 32;
            uint32_t a[2][4];
#pragma unroll
            for (int mt = 0; mt < 2; mt++)
                ldmatrix_x4(a[mt][0], a[mt][1], a[mt][2], a[mt][3],
                            abase + (uint32_t)(aRow + mt * 16) * (KP2 * 4) + kb + aColB);
#pragma unroll
            for (int nt16 = 0; nt16 < 4; nt16++) {
                uint32_t b0, b1, b2, b3;
                ldmatrix_x4(b0, b1, b2, b3,
                            bbase + (uint32_t)(bRow + nt16 * 16) * (KP2 * 4) + kb + bColB);
#pragma unroll
                for (int mt = 0; mt < 2; mt++) {
                    mma_f16(acc[mt][nt16 * 2 + 0], a[mt][0], a[mt][1], a[mt][2], a[mt][3], b0, b1);
                    mma_f16(acc[mt][nt16 * 2 + 1], a[mt][0], a[mt][1], a[mt][2], a[mt][3], b2, b3);
                }
            }
        }
    };

    synthA(0);           // A(0): visible to all after the t=0 barrier
    cpB(0);              // B(0): completed by the t=0 cp_wait
    for (int t = 0; t < kt; t++) {
        cp_wait<0>();    // B(t) landed (this thread's async group)
        __syncthreads(); // all threads' B(t)/A(t) visible; compute(t-1) retired
        if (t + 1 < kt) {
            cpB(t + 1);      // overwrites B buf of retired compute(t-1) — safe
            synthA(t + 1);   // overwrites A buf of retired compute(t-1) — safe
        }
        compute(t & 1);
    }

    // Epilogue: bias + sigmoid, guarded (N = 4624, last tile partial)
#pragma unroll
    for (int mt = 0; mt < 2; mt++) {
        int row = m0 + wm * 32 + mt * 16 + grp;
#pragma unroll
        for (int nt = 0; nt < 8; nt++) {
            int ncl = wn * 64 + nt * 8 + tig * 2;
#pragma unroll
            for (int half = 0; half < 2; half++) {
                int r   = row + half * 8;
                int col = n0 + ncl;
                if (col < N) {
                    float v0 = acc[mt][nt][half * 2 + 0] + bias[col];
                    C[(size_t)r * ldc + col] = 1.0f / (1.0f + __expf(-v0));
                }
                if (col + 1 < N) {
                    float v1 = acc[mt][nt][half * 2 + 1] + bias[col + 1];
                    C[(size_t)r * ldc + col + 1] = 1.0f / (1.0f + __expf(-v1));
                }
            }
        }
    }
}

// ============================ head GEMM (mu / logvar), fp16, BK=32 ============================
__global__ void __launch_bounds__(THREADS, 2)
gemm_head(const __half* __restrict__ Abase, const __half* __restrict__ Wbase,
          const float* __restrict__ bias0, const float* __restrict__ bias1,
          float* __restrict__ Cbase, int batchStrideC)
{
    extern __shared__ unsigned char smem_raw[];
    uint32_t* As = reinterpret_cast<uint32_t*>(smem_raw);
    uint32_t* Bs = As + 2 * STAGEH_U32;

    const int tid = threadIdx.x;
    const int m0  = blockIdx.y * BM;
    const int N = L_, K = E_;

    const int z = blockIdx.z;
    const __half* A    = Abase + (size_t)z * E_;
    const __half* W    = Wbase + (size_t)z * L_ * E_;
    const float* bias  = z ? bias1 : bias0;
    float* C           = Cbase + (size_t)z * batchStrideC;

    const int lane = tid & 31;
    const int warp = tid >> 5;
    const int wm = warp & 3, wn = warp >> 2;
    const int grp = lane >> 2, tig = lane & 3;

    const uint32_t As_b = (uint32_t)__cvta_generic_to_shared(As);
    const uint32_t Bs_b = (uint32_t)__cvta_generic_to_shared(Bs);
    const int aRow  = wm * 32 + ((lane >> 3) & 1) * 8 + (lane & 7);
    const int aColB = (lane >> 4) * 16;
    const int bRow  = wn * 64 + (lane >> 4) * 8 + (lane & 7);
    const int bColB = ((lane >> 3) & 1) * 16;

    auto prefetch = [&](int t) {
        const int buf = t & 1;
        const int k0  = t * 32;
        uint32_t* Ab = As + buf * STAGEH_U32;
        uint32_t* Bb = Bs + buf * STAGEH_U32;
#pragma unroll
        for (int i = 0; i < 2; i++) {
            int q = tid + i * 256;
            int r = q >> 2, ch = q & 3;
            int k = k0 + ch * 8;
            cp_async16(Ab + r * KPADH + ch * 4,
                       A + (size_t)(m0 + r) * (2 * E_) + k, 16);
            const __half* src = W + (size_t)(r < N ? r : 0) * K + k;
            cp_async16(Bb + r * KPADH + ch * 4, src, (r < N) ? 16 : 0);
        }
        cp_commit();
    };

    float acc[2][8][4] = {};

    auto compute = [&](int buf) {
        const uint32_t abase = As_b + buf * STAGE_BYTES;
        const uint32_t bbase = Bs_b + buf * STAGE_BYTES;
#pragma unroll
        for (int kk = 0; kk < 2; kk++) {
            const int kb = kk * 32;
            uint32_t a[2][4];
#pragma unroll
            for (int mt = 0; mt < 2; mt++)
                ldmatrix_x4(a[mt][0], a[mt][1], a[mt][2], a[mt][3],
                            abase + (uint32_t)(aRow + mt * 16) * (KPADH * 4) + kb + aColB);
#pragma unroll
            for (int nt16 = 0; nt16 < 4; nt16++) {
                uint32_t b0, b1, b2, b3;
                ldmatrix_x4(b0, b1, b2, b3,
                            bbase + (uint32_t)(bRow + nt16 * 16) * (KPADH * 4) + kb + bColB);
#pragma unroll
                for (int mt = 0; mt < 2; mt++) {
                    mma_f16(acc[mt][nt16 * 2 + 0], a[mt][0], a[mt][1], a[mt][2], a[mt][3], b0, b1);
                    mma_f16(acc[mt][nt16 * 2 + 1], a[mt][0], a[mt][1], a[mt][2], a[mt][3], b2, b3);
                }
            }
        }
    };

    const int kt = K / 32;
    prefetch(0);
    for (int t = 0; t < kt; t++) {
        if (t + 1 < kt) { prefetch(t + 1); cp_wait<1>(); }
        else            { cp_wait<0>(); }
        __syncthreads();
        compute(t & 1);
        __syncthreads();
    }

#pragma unroll
    for (int mt = 0; mt < 2; mt++) {
        int row = m0 + wm * 32 + mt * 16 + grp;
#pragma unroll
        for (int nt = 0; nt < 8; nt++) {
            int ncl = wn * 64 + nt * 8 + tig * 2;
#pragma unroll
            for (int e = 0; e < 4; e++) {
                int r   = row + ((e >= 2) ? 8 : 0);
                int col = ncl + (e & 1);
                if (col < N)
                    C[(size_t)r * N + col] = acc[mt][nt][e] + bias[col];
            }
        }
    }
}

// ============================ mid kernel ============================
__global__ void __launch_bounds__(256, 1)
mid_kernel(const float* __restrict__ mu, const float* __restrict__ logvar,
           const float* __restrict__ eps,
           const float* __restrict__ W3, const float* __restrict__ b3,
           const float* __restrict__ W4, const float* __restrict__ b4,
           const float* __restrict__ W5, const float* __restrict__ b5,
           const float* __restrict__ fcy_w, const float* __restrict__ fcy_b,
           float* __restrict__ h51, float* __restrict__ y)
{
    extern __shared__ unsigned char smem_raw[];
    float* s   = reinterpret_cast<float*>(smem_raw);
    float* sW3 = s;
    float* sW4 = sW3 + L_ * 69;
    float* sW5 = sW4 + L_ * 69;
    float* sb3 = sW5 + L_ * 69;
    float* sb4 = sb3 + L_;
    float* sb5 = sb4 + L_;
    float* zs  = sb5 + L_;
    float* h3s = zs + 8 * L_;
    float* h4s = h3s + 8 * L_;

    const int tid = threadIdx.x;
    for (int idx = tid; idx < L_ * L_; idx += 256) {
        int o = idx / L_, d = idx - o * L_;
        sW3[o * 69 + d] = W3[idx];
        sW4[o * 69 + d] = W4[idx];
        sW5[o * 69 + d] = W5[idx];
    }
    for (int idx = tid; idx < L_; idx += 256) {
        sb3[idx] = b3[idx]; sb4[idx] = b4[idx]; sb5[idx] = b5[idx];
    }
    __syncthreads();

    const int lane = tid & 31, w = tid >> 5;
    const int row = blockIdx.x * 8 + w;
    const float* murow  = mu + (size_t)row * L_;
    const float* lvrow  = logvar + (size_t)row * L_;
    const float* epsrow = eps + (size_t)row * L_;
    float* zw  = zs + w * L_;
    float* h3w = h3s + w * L_;
    float* h4w = h4s + w * L_;

    float yp = 0.f;
    for (int o = lane; o < L_; o += 32) {
        float m_ = murow[o];
        zw[o] = m_ + epsrow[o] * expf(0.5f * lvrow[o]);
        yp += m_ * fcy_w[o];
    }
#pragma unroll
    for (int off = 16; off; off >>= 1) yp += __shfl_xor_sync(0xffffffffu, yp, off);
    if (lane == 0) y[row] = yp + fcy_b[0];
    __syncwarp();

    for (int o = lane; o < L_; o += 32) {
        float sacc = sb3[o];
        const float* wr = sW3 + o * 69;
#pragma unroll 4
        for (int d = 0; d < L_; d++) sacc += zw[d] * wr[d];
        h3w[o] = sacc;                  // branch 0: NO sigmoid
    }
    __syncwarp();
    for (int o = lane; o < L_; o += 32) {
        float sacc = sb4[o];
        const float* wr = sW4 + o * 69;
#pragma unroll 4
        for (int d = 0; d < L_; d++) sacc += h3w[d] * wr[d];
        h4w[o] = 1.0f / (1.0f + expf(-sacc));
    }
    __syncwarp();
    for (int o = lane; o < L_; o += 32) {
        float sacc = sb5[o];
        const float* wr = sW5 + o * 69;
#pragma unroll 4
        for (int d = 0; d < L_; d++) sacc += h4w[d] * wr[d];
        h51[(size_t)row * L_ + o] = sacc;
    }
}

// ============================ launch ============================
extern "C" void kernel_launch(void* const* d_in, const int* in_sizes, int n_in,
                              void* d_out, int out_size)
{
    const float* x      = (const float*)d_in[0];
    const float* eps    = (const float*)d_in[1];
    const float* fc11_w = (const float*)d_in[2];
    const float* fc11_b = (const float*)d_in[3];
    const float* fc12_w = (const float*)d_in[4];
    const float* fc12_b = (const float*)d_in[5];
    const float* fc21_w = (const float*)d_in[6];
    const float* fc21_b = (const float*)d_in[7];
    const float* fc22_w = (const float*)d_in[8];
    const float* fc22_b = (const float*)d_in[9];
    const float* W3     = (const float*)d_in[10];
    const float* b3     = (const float*)d_in[11];
    const float* W4     = (const float*)d_in[12];
    const float* b4     = (const float*)d_in[13];
    const float* W5     = (const float*)d_in[14];
    const float* b5     = (const float*)d_in[15];
    const float* fc6_w  = (const float*)d_in[16];
    const float* fc6_b  = (const float*)d_in[17];
    const float* fcy_w  = (const float*)d_in[18];
    const float* fcy_b  = (const float*)d_in[19];

    float* out   = (float*)d_out;
    float* recon = out;
    float* mu    = out + (size_t)B_ * D_;
    float* lv    = mu + (size_t)B_ * L_;
    float* y     = lv + (size_t)B_ * L_;

    __half*   x16;  cudaGetSymbolAddress((void**)&x16, g_x16);
    __half*   h16;  cudaGetSymbolAddress((void**)&h16, g_h16);
    __half*   w1h;  cudaGetSymbolAddress((void**)&w1h, g_w1h);
    __half*   w2h;  cudaGetSymbolAddress((void**)&w2h, g_w2h);
    __half*   w6s;  cudaGetSymbolAddress((void**)&w6s, g_w6s);
    uint16_t* prs;  cudaGetSymbolAddress((void**)&prs, g_pairs);
    float*    h51;  cudaGetSymbolAddress((void**)&h51, g_h51);
    float*    b1;   cudaGetSymbolAddress((void**)&b1,  g_b1);

    // fused pre-pass (1 launch) + pair table + symmetric weight fold
    prep_all<<<1024, 256>>>((const float4*)x,
                            (const float4*)fc11_w, (const float4*)fc12_w,
                            (const float4*)fc21_w, (const float4*)fc22_w,
                            (const float4*)fc11_b, (const float4*)fc12_b,
                            (uint2*)x16, (uint2*)w1h, (uint2*)w2h, (float4*)b1);
    build_pairs<<<(KS_PAD + 255) / 256, 256>>>(prs);
    build_w6s<<<D_, 256>>>(fc6_w, prs, w6s);

    const size_t smemEnc  = (size_t)6 * STG2_B;                                 // 110592
    const size_t smemRec  = (size_t)(128 * L_ * 4) + KS_PAD * 2 + 4 * STG2_B;   // 113280
    const size_t smemHead = (size_t)4 * STAGE_BYTES;                            // 40960
    const size_t smemMid  = (size_t)(3 * L_ * 69 + 3 * L_ + 3 * 8 * L_) * 4;

    cudaFuncSetAttribute(gemm_enc,   cudaFuncAttributeMaxDynamicSharedMemorySize, (int)smemEnc);
    cudaFuncSetAttribute(gemm_rec,   cudaFuncAttributeMaxDynamicSharedMemorySize, (int)smemRec);
    cudaFuncSetAttribute(gemm_head,  cudaFuncAttributeMaxDynamicSharedMemorySize, (int)smemHead);
    cudaFuncSetAttribute(mid_kernel, cudaFuncAttributeMaxDynamicSharedMemorySize, (int)smemMid);

    // 1) h16 = fp16(relu(x @ [fc11|fc12]^T + b))   [4096 x 2048]
    gemm_enc<<<dim3(2 * E_ / BN, B_ / BM), THREADS, smemEnc>>>(x16, w1h, b1, h16);

    // 2) mu / logvar heads  [4096 x 68], z-batched
    gemm_head<<<dim3(1, B_ / BM, 2), THREADS, smemHead>>>(
        h16, w2h, fc21_b, fc22_b, mu, B_ * L_);

    // 3) reparam + y + decoder branch 0 -> h51
    mid_kernel<<<B_ / 8, 256, smemMid>>>(
        mu, lv, eps, W3, b3, W4, b4, W5, b5, fcy_w, fcy_b, h51, y);

    // 4) recon = sigmoid(sympairs(h51) @ w6s^T + b)  [4096 x 4624], K=2368
    gemm_rec<<<dim3((D_ + BN - 1) / BN, B_ / BM), THREADS, smemRec>>>(
        w6s, fc6_b, h51, prs, recon);
}